// round 1
// baseline (speedup 1.0000x reference)
#include <cuda_runtime.h>
#include <math.h>

// ---------------- problem constants ----------------
#define BB   2
#define SS   8192
#define DD   1024
#define HH   16
#define DKK  64
#define BLK  512      // local block size
#define NBLK 16
#define GG   128      // global tokens

// ---------------- scratch (device globals; no allocation allowed) ----------
__device__ float d_lq[BB*HH*SS*DKK];    // [B,H,S,64]
__device__ float d_lk[BB*HH*SS*DKK];
__device__ float d_lv[BB*HH*SS*DKK];
__device__ float d_gq[BB*HH*GG*DKK];    // [B,H,G,64]
__device__ float d_gk[BB*HH*GG*DKK];
__device__ float d_gv[BB*HH*GG*DKK];
__device__ float d_lctx[(size_t)BB*SS*DD];  // [B,S,D]  (h-major cols: h*64+f)
__device__ float d_gctx[(size_t)BB*GG*DD];  // [B,G,D]

// ============================================================================
// Generic GEMM:  C[m,n] = (sum_k A[m,k] * W[n,k] + bias[n]) * scale
// A: row-major [M,1024], W: row-major [1024,1024] (torch Linear weight).
// Tile 128x128, BK=16, 256 threads, 8x8 microtile per thread.
// out_sel 0..5 -> head-split scratch buffers; 6 -> plain [M,1024] at outp.
// in_sel  0 -> Ain param; 1 -> d_lctx; 2 -> d_gctx.
// ============================================================================
__global__ void __launch_bounds__(256, 2) gemm_proj(
    const float* __restrict__ Ain,
    const float* __restrict__ W,
    const float* __restrict__ bias,
    int M, int Lrows, float scale,
    int in_sel, int out_sel, float* __restrict__ outp)
{
    __shared__ float Ast[16][132];   // [k][m], padded
    __shared__ float Wst[16][132];   // [k][n], padded

    const float* A = Ain;
    if (in_sel == 1)      A = d_lctx;
    else if (in_sel == 2) A = d_gctx;

    const int m0  = blockIdx.x * 128;
    const int n0  = blockIdx.y * 128;
    const int tid = threadIdx.x;
    const int tx  = tid & 15;
    const int ty  = tid >> 4;
    const int r_l = tid >> 1;           // 0..127 : tile row loaded by this thread
    const int k_l = (tid & 1) * 8;      // 0 or 8 : k-offset

    float acc[8][8];
#pragma unroll
    for (int i = 0; i < 8; ++i)
#pragma unroll
        for (int j = 0; j < 8; ++j) acc[i][j] = 0.f;

    const float* Arow = A + (size_t)(m0 + r_l) * 1024 + k_l;
    const float* Wrow = W + (size_t)(n0 + r_l) * 1024 + k_l;

    for (int kt = 0; kt < 1024; kt += 16) {
        float4 a0 = *(const float4*)(Arow + kt);
        float4 a1 = *(const float4*)(Arow + kt + 4);
        float4 w0 = *(const float4*)(Wrow + kt);
        float4 w1 = *(const float4*)(Wrow + kt + 4);
        Ast[k_l+0][r_l] = a0.x; Ast[k_l+1][r_l] = a0.y;
        Ast[k_l+2][r_l] = a0.z; Ast[k_l+3][r_l] = a0.w;
        Ast[k_l+4][r_l] = a1.x; Ast[k_l+5][r_l] = a1.y;
        Ast[k_l+6][r_l] = a1.z; Ast[k_l+7][r_l] = a1.w;
        Wst[k_l+0][r_l] = w0.x; Wst[k_l+1][r_l] = w0.y;
        Wst[k_l+2][r_l] = w0.z; Wst[k_l+3][r_l] = w0.w;
        Wst[k_l+4][r_l] = w1.x; Wst[k_l+5][r_l] = w1.y;
        Wst[k_l+6][r_l] = w1.z; Wst[k_l+7][r_l] = w1.w;
        __syncthreads();

#pragma unroll
        for (int k = 0; k < 16; ++k) {
            float4 af0 = *(const float4*)&Ast[k][ty*8];
            float4 af1 = *(const float4*)&Ast[k][ty*8+4];
            float4 bf0 = *(const float4*)&Wst[k][tx*8];
            float4 bf1 = *(const float4*)&Wst[k][tx*8+4];
            float a[8] = {af0.x,af0.y,af0.z,af0.w,af1.x,af1.y,af1.z,af1.w};
            float b[8] = {bf0.x,bf0.y,bf0.z,bf0.w,bf1.x,bf1.y,bf1.z,bf1.w};
#pragma unroll
            for (int i = 0; i < 8; ++i)
#pragma unroll
                for (int j = 0; j < 8; ++j)
                    acc[i][j] = fmaf(a[i], b[j], acc[i][j]);
        }
        __syncthreads();
    }

    float bj[8];
#pragma unroll
    for (int j = 0; j < 8; ++j) bj[j] = bias[n0 + tx*8 + j];

    if (out_sel == 6) {
        // plain [M,1024]
#pragma unroll
        for (int i = 0; i < 8; ++i) {
            size_t m = (size_t)(m0 + ty*8 + i);
            float* o = outp + m * 1024 + n0 + tx*8;
            float4 v0, v1;
            v0.x = (acc[i][0]+bj[0])*scale; v0.y = (acc[i][1]+bj[1])*scale;
            v0.z = (acc[i][2]+bj[2])*scale; v0.w = (acc[i][3]+bj[3])*scale;
            v1.x = (acc[i][4]+bj[4])*scale; v1.y = (acc[i][5]+bj[5])*scale;
            v1.z = (acc[i][6]+bj[6])*scale; v1.w = (acc[i][7]+bj[7])*scale;
            *(float4*)o       = v0;
            *(float4*)(o + 4) = v1;
        }
    } else {
        // head-split [B,H,Lrows,64]; within a thread the 8 cols stay in 1 head
        float* T = (out_sel==0) ? d_lq : (out_sel==1) ? d_lk : (out_sel==2) ? d_lv :
                   (out_sel==3) ? d_gq : (out_sel==4) ? d_gk : d_gv;
        int nb = n0 + tx*8;
        int h  = nb >> 6;
        int f  = nb & 63;
#pragma unroll
        for (int i = 0; i < 8; ++i) {
            int m = m0 + ty*8 + i;
            int b = m / Lrows;
            int s = m - b * Lrows;
            float* o = T + ((((size_t)(b*HH + h)) * Lrows + s) << 6) + f;
            float4 v0, v1;
            v0.x = (acc[i][0]+bj[0])*scale; v0.y = (acc[i][1]+bj[1])*scale;
            v0.z = (acc[i][2]+bj[2])*scale; v0.w = (acc[i][3]+bj[3])*scale;
            v1.x = (acc[i][4]+bj[4])*scale; v1.y = (acc[i][5]+bj[5])*scale;
            v1.z = (acc[i][6]+bj[6])*scale; v1.w = (acc[i][7]+bj[7])*scale;
            *(float4*)o       = v0;
            *(float4*)(o + 4) = v1;
        }
    }
}

// ============================================================================
// Fused flash-style attention. CTA = 32 query rows, keys streamed in 64-chunks.
// Keys = [global keys gk (128, no mask)] ++ [local segment lk (mask added)].
// mode 0: local block attention (q-rows from lq, keys from this block)
// mode 1: global attention (q-rows from gq, keys = gk ++ ALL lk; logits*0.125)
// 128 threads = 16x8 grid, 4x4 microtile; online softmax per row with
// 16-lane shfl reductions (lanes sharing ty within a warp).
// ============================================================================
__global__ void __launch_bounds__(128) attn_kernel(const float* __restrict__ mask, int mode)
{
    __shared__ float Qst[64*36];    // Q^T [dim][row], pitch 36
    __shared__ float KPst[64*68];   // K^T [dim][key] pitch 68; reused as P [key][row]
    __shared__ float Vs[64*64];     // V   [key][dim]

    const int tid  = threadIdx.x;
    const int tx   = tid & 15;
    const int ty   = tid >> 4;       // 0..7
    const int lane = tid & 31;
    const int w    = tid >> 5;       // 4 warps
    const int tx4  = tx * 4;
    const int ty4  = ty * 4;

    const float *qb, *gkb, *gvb, *lkb, *lvb, *mb;
    float* ctxb;
    float ps;
    int L2;

    if (mode == 0) {
        int bi = blockIdx.x;
        int qt = bi & 15; bi >>= 4;
        int n  = bi & 15; bi >>= 4;
        int h  = bi & 15;
        int b  = bi >> 4;
        size_t bh = (size_t)(b*HH + h);
        qb   = d_lq + (bh*SS + n*BLK + qt*32) * 64;
        gkb  = d_gk + bh*GG*64;
        gvb  = d_gv + bh*GG*64;
        lkb  = d_lk + (bh*SS + n*BLK) * 64;
        lvb  = d_lv + (bh*SS + n*BLK) * 64;
        mb   = mask + b*SS + n*BLK;
        ctxb = d_lctx + ((size_t)b*SS + n*BLK + qt*32) * DD + h*64;
        ps = 1.0f; L2 = BLK;
    } else {
        int bi = blockIdx.x;
        int qt = bi & 3; bi >>= 2;
        int h  = bi & 15;
        int b  = bi >> 4;
        size_t bh = (size_t)(b*HH + h);
        qb   = d_gq + (bh*GG + qt*32) * 64;
        gkb  = d_gk + bh*GG*64;
        gvb  = d_gv + bh*GG*64;
        lkb  = d_lk + bh*SS*64;
        lvb  = d_lv + bh*SS*64;
        mb   = mask + b*SS;
        ctxb = d_gctx + ((size_t)b*GG + qt*32) * DD + h*64;
        ps = 0.125f; L2 = SS;   // logits get scaled by 1/sqrt(dk) AGAIN (ref-faithful)
    }

    // Load Q transposed: 32 rows, 8 rows per warp.
#pragma unroll
    for (int r = 0; r < 8; ++r) {
        int row = w*8 + r;
        Qst[lane*36 + row]        = qb[row*64 + lane];
        Qst[(lane+32)*36 + row]   = qb[row*64 + lane + 32];
    }

    float m_r[4], l_r[4], acc[4][4];
#pragma unroll
    for (int i = 0; i < 4; ++i) {
        m_r[i] = -1e30f; l_r[i] = 0.f;
#pragma unroll
        for (int j = 0; j < 4; ++j) acc[i][j] = 0.f;
    }

    const int nch = 2 + (L2 >> 6);
    for (int c = 0; c < nch; ++c) {
        const float *kc, *vc, *mr = nullptr;
        if (c < 2) { kc = gkb + c*4096;              vc = gvb + c*4096; }
        else       { kc = lkb + (size_t)(c-2)*4096;  vc = lvb + (size_t)(c-2)*4096;
                     mr = mb + (c-2)*64; }

        __syncthreads();   // previous P.V GEMM finished with KPst/Vs

        // K chunk transposed: 64 rows, 16 per warp
#pragma unroll
        for (int r = 0; r < 16; ++r) {
            int row = w*16 + r;
            KPst[lane*68 + row]      = kc[row*64 + lane];
            KPst[(lane+32)*68 + row] = kc[row*64 + lane + 32];
        }
        // V chunk straight copy (float4)
#pragma unroll
        for (int i = 0; i < 8; ++i)
            ((float4*)Vs)[tid + i*128] = ((const float4*)vc)[tid + i*128];

        float mk[4];
#pragma unroll
        for (int j = 0; j < 4; ++j) mk[j] = mr ? __ldg(mr + tx4 + j) : 0.f;

        __syncthreads();

        // ---- scores: S = Q . K^T  (32x64, k over 64 dims) ----
        float s[4][4];
#pragma unroll
        for (int i = 0; i < 4; ++i)
#pragma unroll
            for (int j = 0; j < 4; ++j) s[i][j] = 0.f;

#pragma unroll
        for (int k = 0; k < 64; ++k) {
            float4 aq = *(const float4*)&Qst[k*36 + ty4];
            float4 bk = *(const float4*)&KPst[k*68 + tx4];
            float a_[4] = {aq.x, aq.y, aq.z, aq.w};
            float b_[4] = {bk.x, bk.y, bk.z, bk.w};
#pragma unroll
            for (int i = 0; i < 4; ++i)
#pragma unroll
                for (int j = 0; j < 4; ++j)
                    s[i][j] = fmaf(a_[i], b_[j], s[i][j]);
        }
#pragma unroll
        for (int i = 0; i < 4; ++i)
#pragma unroll
            for (int j = 0; j < 4; ++j)
                s[i][j] = s[i][j] * ps + mk[j];

        // ---- online softmax update (row stats across the 16 tx lanes) ----
#pragma unroll
        for (int i = 0; i < 4; ++i) {
            float mc = fmaxf(fmaxf(s[i][0], s[i][1]), fmaxf(s[i][2], s[i][3]));
            mc = fmaxf(mc, __shfl_xor_sync(0xffffffffu, mc, 8));
            mc = fmaxf(mc, __shfl_xor_sync(0xffffffffu, mc, 4));
            mc = fmaxf(mc, __shfl_xor_sync(0xffffffffu, mc, 2));
            mc = fmaxf(mc, __shfl_xor_sync(0xffffffffu, mc, 1));
            float mn    = fmaxf(m_r[i], mc);
            float alpha = __expf(m_r[i] - mn);
            m_r[i] = mn;
            float rs = 0.f;
#pragma unroll
            for (int j = 0; j < 4; ++j) { s[i][j] = __expf(s[i][j] - mn); rs += s[i][j]; }
            rs += __shfl_xor_sync(0xffffffffu, rs, 8);
            rs += __shfl_xor_sync(0xffffffffu, rs, 4);
            rs += __shfl_xor_sync(0xffffffffu, rs, 2);
            rs += __shfl_xor_sync(0xffffffffu, rs, 1);
            l_r[i] = l_r[i] * alpha + rs;
#pragma unroll
            for (int j = 0; j < 4; ++j) acc[i][j] *= alpha;
        }

        __syncthreads();   // all warps done reading K^T from KPst

        // write P (overlay on KPst): P[key][row]
#pragma unroll
        for (int j = 0; j < 4; ++j) {
            float4 pv = make_float4(s[0][j], s[1][j], s[2][j], s[3][j]);
            *(float4*)&KPst[(tx4 + j)*68 + ty4] = pv;
        }
        __syncthreads();

        // ---- acc += P . V  (32x64, k over 64 keys) ----
#pragma unroll
        for (int kk = 0; kk < 64; ++kk) {
            float4 ap = *(const float4*)&KPst[kk*68 + ty4];
            float4 bv = *(const float4*)&Vs[kk*64 + tx4];
            float a_[4] = {ap.x, ap.y, ap.z, ap.w};
            float b_[4] = {bv.x, bv.y, bv.z, bv.w};
#pragma unroll
            for (int i = 0; i < 4; ++i)
#pragma unroll
                for (int j = 0; j < 4; ++j)
                    acc[i][j] = fmaf(a_[i], b_[j], acc[i][j]);
        }
    }

    // epilogue: divide by l, write ctx [row, h*64 + f]
#pragma unroll
    for (int i = 0; i < 4; ++i) {
        float inv = 1.0f / l_r[i];
        float4 o = make_float4(acc[i][0]*inv, acc[i][1]*inv,
                               acc[i][2]*inv, acc[i][3]*inv);
        *(float4*)&ctxb[(size_t)(ty4 + i) * DD + tx4] = o;
    }
}

// ============================================================================
extern "C" void kernel_launch(void* const* d_in, const int* in_sizes, int n_in,
                              void* d_out, int out_size) {
    (void)in_sizes; (void)n_in; (void)out_size;
    const float* Q    = (const float*)d_in[0];
    const float* K    = (const float*)d_in[1];
    const float* V    = (const float*)d_in[2];
    const float* Gt   = (const float*)d_in[3];
    const float* mask = (const float*)d_in[4];
    const float* Wq = (const float*)d_in[5];
    const float* bq = (const float*)d_in[6];
    const float* Wk = (const float*)d_in[7];
    const float* bk = (const float*)d_in[8];
    const float* Wv = (const float*)d_in[9];
    const float* bv = (const float*)d_in[10];
    const float* Wo = (const float*)d_in[11];
    const float* bo = (const float*)d_in[12];
    float* out = (float*)d_out;

    const float scale = 0.125f;   // 1/sqrt(64)
    dim3 blk(256);
    dim3 gL(16384/128, 8);        // local-token projections / out-proj
    dim3 gG(256/128, 8);          // global-token projections / out-proj

    // projections -> head-split scratch
    gemm_proj<<<gL, blk>>>(Q,  Wq, bq, 16384, 8192, scale, 0, 0, nullptr); // lq
    gemm_proj<<<gL, blk>>>(K,  Wk, bk, 16384, 8192, 1.0f,  0, 1, nullptr); // lk
    gemm_proj<<<gL, blk>>>(V,  Wv, bv, 16384, 8192, 1.0f,  0, 2, nullptr); // lv
    gemm_proj<<<gG, blk>>>(Gt, Wq, bq,   256,  128, scale, 0, 3, nullptr); // gq
    gemm_proj<<<gG, blk>>>(Gt, Wk, bk,   256,  128, 1.0f,  0, 4, nullptr); // gk
    gemm_proj<<<gG, blk>>>(Gt, Wv, bv,   256,  128, 1.0f,  0, 5, nullptr); // gv

    // attention
    attn_kernel<<<8192, 128>>>(mask, 0);  // local: B*H*N*(512/32)
    attn_kernel<<<128,  128>>>(mask, 1);  // global: B*H*(128/32)

    // output projections: local_out then global_out (tuple flatten order)
    gemm_proj<<<gL, blk>>>(nullptr, Wo, bo, 16384, 8192, 1.0f, 1, 6, out);
    gemm_proj<<<gG, blk>>>(nullptr, Wo, bo,   256,  128, 1.0f, 2, 6,
                           out + (size_t)BB*SS*DD);
}

// round 3
// speedup vs baseline: 1.8839x; 1.8839x over previous
#include <cuda_runtime.h>
#include <cuda_bf16.h>
#include <math.h>
#include <stdint.h>

// ---------------- problem constants ----------------
#define BB   2
#define SS   8192
#define DD   1024
#define HH   16
#define BLK  512
#define GG   128

// ---------------- fp32 scratch ----------------
__device__ float d_lq[(size_t)BB*HH*SS*64];
__device__ float d_lk[(size_t)BB*HH*SS*64];
__device__ float d_lv[(size_t)BB*HH*SS*64];
__device__ float d_gq[(size_t)BB*HH*GG*64];
__device__ float d_gk[(size_t)BB*HH*GG*64];
__device__ float d_gv[(size_t)BB*HH*GG*64];
__device__ float d_lctx[(size_t)BB*SS*DD];
__device__ float d_gctx[(size_t)BB*GG*DD];

// ---------------- bf16 [hi|lo] operands (cols 0..1023 = hi, 1024..2047 = lo) --
__device__ __nv_bfloat16 d_Q2 [(size_t)16384*2048];
__device__ __nv_bfloat16 d_K2 [(size_t)16384*2048];
__device__ __nv_bfloat16 d_V2 [(size_t)16384*2048];
__device__ __nv_bfloat16 d_G2 [(size_t)256*2048];
__device__ __nv_bfloat16 d_C2 [(size_t)16384*2048];
__device__ __nv_bfloat16 d_Cg2[(size_t)256*2048];
__device__ __nv_bfloat16 d_Wq2[(size_t)1024*2048];
__device__ __nv_bfloat16 d_Wk2[(size_t)1024*2048];
__device__ __nv_bfloat16 d_Wv2[(size_t)1024*2048];
__device__ __nv_bfloat16 d_Wo2[(size_t)1024*2048];

// ---------------- helpers ----------------
__device__ __forceinline__ uint32_t smem_u32(const void* p) {
    uint32_t a;
    asm("{ .reg .u64 t; cvta.to.shared.u64 t, %1; cvt.u32.u64 %0, t; }"
        : "=r"(a) : "l"(p));
    return a;
}
__device__ __forceinline__ void ldsm_x4(uint32_t* r, uint32_t addr) {
    asm volatile("ldmatrix.sync.aligned.m8n8.x4.shared.b16 {%0,%1,%2,%3}, [%4];"
                 : "=r"(r[0]), "=r"(r[1]), "=r"(r[2]), "=r"(r[3]) : "r"(addr));
}
__device__ __forceinline__ void mma_bf16(float* d, const uint32_t* a, const uint32_t* b) {
    asm volatile("mma.sync.aligned.m16n8k16.row.col.f32.bf16.bf16.f32 "
                 "{%0,%1,%2,%3}, {%4,%5,%6,%7}, {%8,%9}, {%0,%1,%2,%3};"
                 : "+f"(d[0]), "+f"(d[1]), "+f"(d[2]), "+f"(d[3])
                 : "r"(a[0]), "r"(a[1]), "r"(a[2]), "r"(a[3]),
                   "r"(b[0]), "r"(b[1]));
}

// ============================================================================
// conv_split: fp32 [M,1024] -> bf16 [M,2048] = [hi(1024) | lo(1024)]
// ============================================================================
__global__ void conv_split(const float* __restrict__ X0, const float* __restrict__ X1,
                           const float* __restrict__ X2, const float* __restrict__ X3,
                           __nv_bfloat16* __restrict__ Y0, __nv_bfloat16* __restrict__ Y1,
                           __nv_bfloat16* __restrict__ Y2, __nv_bfloat16* __restrict__ Y3)
{
    int z = blockIdx.z;
    const float* X = (z==0)?X0:(z==1)?X1:(z==2)?X2:X3;
    __nv_bfloat16* Y = (z==0)?Y0:(z==1)?Y1:(z==2)?Y2:Y3;
    size_t row = blockIdx.x;
    int col = threadIdx.x * 4;
    float4 x = *(const float4*)(X + row*1024 + col);
    __nv_bfloat16 h0 = __float2bfloat16(x.x);
    __nv_bfloat16 h1 = __float2bfloat16(x.y);
    __nv_bfloat16 h2 = __float2bfloat16(x.z);
    __nv_bfloat16 h3 = __float2bfloat16(x.w);
    __nv_bfloat16 l0 = __float2bfloat16(x.x - __bfloat162float(h0));
    __nv_bfloat16 l1 = __float2bfloat16(x.y - __bfloat162float(h1));
    __nv_bfloat16 l2 = __float2bfloat16(x.z - __bfloat162float(h2));
    __nv_bfloat16 l3 = __float2bfloat16(x.w - __bfloat162float(h3));
    __nv_bfloat162* ph = (__nv_bfloat162*)(Y + row*2048 + col);
    __nv_bfloat162* pl = (__nv_bfloat162*)(Y + row*2048 + 1024 + col);
    ph[0] = __halves2bfloat162(h0, h1);
    ph[1] = __halves2bfloat162(h2, h3);
    pl[0] = __halves2bfloat162(l0, l1);
    pl[1] = __halves2bfloat162(l2, l3);
}

// ============================================================================
// gemm_tc: C[m,n] = (sum_k A[m,k]*W[n,k] + bias[n]) * scale  via bf16x3 on
// mma.sync.m16n8k16 (base-target tensor path; no tcgen05 at compute_103).
// Virtual K' = 3072 over 48 chunks of 64 bf16:
//   chunks  0-15: Ahi.Whi   16-31: Ahi.Wlo   32-47: Alo.Whi
// CTA tile 128x128, 3-stage cp.async pipeline, 256 threads = 8 warps (4x2),
// warp tile 32x64 (2 m16 x 8 n8 fragments).
// ============================================================================
#define NST  3
#define STB  32768
#define NCH  48
#define GEMM_SMEM (NST*STB)

__global__ void __launch_bounds__(256) gemm_tc(
    const __nv_bfloat16* __restrict__ A0, const __nv_bfloat16* __restrict__ A1,
    const __nv_bfloat16* __restrict__ A2,
    const __nv_bfloat16* __restrict__ W0, const __nv_bfloat16* __restrict__ W1,
    const __nv_bfloat16* __restrict__ W2,
    const float* __restrict__ Bi0, const float* __restrict__ Bi1,
    const float* __restrict__ Bi2,
    int Lrows, int mode, float* __restrict__ outp)
{
    extern __shared__ char smem[];
    const uint32_t sb  = smem_u32(smem);
    const int tid  = threadIdx.x;
    const int wid  = tid >> 5;
    const int lane = tid & 31;
    const int z    = blockIdx.z;

    const __nv_bfloat16* A = (z==0)?A0:(z==1)?A1:A2;
    const __nv_bfloat16* W = (z==0)?W0:(z==1)?W1:W2;
    const float* bias      = (z==0)?Bi0:(z==1)?Bi1:Bi2;

    const int m0 = blockIdx.x * 128;
    const int n0 = blockIdx.y * 128;
    float scale = 1.0f;
    int out_sel = 6;
    if (mode == 0)      { out_sel = z;     if (z==0) scale = 0.125f; }
    else if (mode == 1) { out_sel = 3 + z; if (z==0) scale = 0.125f; }

    // ---- async loads: thread tid covers rows tid>>3 (+32i), 16B unit tid&7 --
    const int      r0  = tid >> 3;
    const int      c16 = tid & 7;
    const uint32_t swo = (uint32_t)(tid*16) ^ ((uint32_t)(tid*2) & 0x70);
    const __nv_bfloat16* Abase = A + (size_t)(m0 + r0)*2048 + c16*8;
    const __nv_bfloat16* Wbase = W + (size_t)(n0 + r0)*2048 + c16*8;

    auto load_stage = [&](int stage, int c) {
        const int aIdx = (c < 16) ? c : c - 16;   // A: hi,hi,lo
        const int wIdx = (c < 32) ? c : c - 32;   // W: hi,lo,hi
        const __nv_bfloat16* ga = Abase + aIdx*64;
        const __nv_bfloat16* gw = Wbase + wIdx*64;
        const uint32_t smA = sb + stage*STB;
        const uint32_t smB = smA + 16384;
#pragma unroll
        for (int i = 0; i < 4; ++i)
            asm volatile("cp.async.cg.shared.global [%0], [%1], 16;"
                         :: "r"(smA + swo + i*4096), "l"(ga + (size_t)i*32*2048));
#pragma unroll
        for (int i = 0; i < 4; ++i)
            asm volatile("cp.async.cg.shared.global [%0], [%1], 16;"
                         :: "r"(smB + swo + i*4096), "l"(gw + (size_t)i*32*2048));
        asm volatile("cp.async.commit_group;" ::: "memory");
    };

    // ---- per-warp fragment geometry ----
    const int wr = wid & 3;       // m sub-block (32 rows)
    const int wc = wid >> 2;      // n sub-block (64 cols)

    // A ldmatrix address pieces: row = wr*32 + t*16 + (lane&15), kb += lane>>4
    const int arow = wr*32 + (lane & 15);
    const int akb  = lane >> 4;
    // B: g = lane>>3 ; row = wc*64 + u*16 + (g>>1)*8 + (lane&7), kb += g&1
    const int g    = lane >> 3;
    const int brow = wc*64 + (g >> 1)*8 + (lane & 7);
    const int bkb  = g & 1;

    float acc[2][8][4];
#pragma unroll
    for (int t = 0; t < 2; ++t)
#pragma unroll
        for (int j = 0; j < 8; ++j)
#pragma unroll
            for (int e = 0; e < 4; ++e) acc[t][j][e] = 0.f;

    load_stage(0, 0);
    load_stage(1, 1);

    for (int c = 0; c < NCH; ++c) {
        if (c < NCH-1) asm volatile("cp.async.wait_group 1;" ::: "memory");
        else           asm volatile("cp.async.wait_group 0;" ::: "memory");
        __syncthreads();

        if (c + 2 < NCH) load_stage((c+2) % NST, c+2);

        const uint32_t smA = sb + (c % NST)*STB;
        const uint32_t smB = smA + 16384;

#pragma unroll
        for (int ks = 0; ks < 4; ++ks) {
            const int kb = ks*2;
            uint32_t af[2][4];
#pragma unroll
            for (int t = 0; t < 2; ++t) {
                int row = arow + t*16;
                uint32_t off = (uint32_t)(row*128 + (kb + akb)*16);
                ldsm_x4(af[t], smA + (off ^ ((row & 7) * 16)));
            }
            uint32_t bf[4][4];
#pragma unroll
            for (int u = 0; u < 4; ++u) {
                int row = brow + u*16;
                uint32_t off = (uint32_t)(row*128 + (kb + bkb)*16);
                ldsm_x4(bf[u], smB + (off ^ ((row & 7) * 16)));
            }
#pragma unroll
            for (int t = 0; t < 2; ++t)
#pragma unroll
                for (int j = 0; j < 8; ++j)
                    mma_bf16(acc[t][j], af[t], &bf[j>>1][(j&1)*2]);
        }
    }
    __syncthreads();

    // ---- epilogue: bias + scale + scatter ----
#pragma unroll
    for (int t = 0; t < 2; ++t) {
        const int r1 = m0 + wr*32 + t*16 + (lane >> 2);
        const int r2 = r1 + 8;
#pragma unroll
        for (int j = 0; j < 8; ++j) {
            const int nb = n0 + wc*64 + j*8 + (lane & 3)*2;
            float2 bv = *(const float2*)(bias + nb);
            float2 v1, v2;
            v1.x = (acc[t][j][0] + bv.x) * scale;
            v1.y = (acc[t][j][1] + bv.y) * scale;
            v2.x = (acc[t][j][2] + bv.x) * scale;
            v2.y = (acc[t][j][3] + bv.y) * scale;
            if (out_sel == 6) {
                *(float2*)(outp + (size_t)r1 * 1024 + nb) = v1;
                *(float2*)(outp + (size_t)r2 * 1024 + nb) = v2;
            } else {
                float* T = (out_sel==0) ? d_lq : (out_sel==1) ? d_lk :
                           (out_sel==2) ? d_lv : (out_sel==3) ? d_gq :
                           (out_sel==4) ? d_gk : d_gv;
                const int h = nb >> 6;
                const int f = nb & 63;
                int b1 = r1 / Lrows, s1 = r1 - b1 * Lrows;
                int b2 = r2 / Lrows, s2 = r2 - b2 * Lrows;
                *(float2*)(T + ((((size_t)(b1*HH + h)) * Lrows + s1) << 6) + f) = v1;
                *(float2*)(T + ((((size_t)(b2*HH + h)) * Lrows + s2) << 6) + f) = v2;
            }
        }
    }
}

// ============================================================================
// Fused flash-style attention (fp32, unchanged / known-good).
// ============================================================================
__global__ void __launch_bounds__(128) attn_kernel(const float* __restrict__ mask, int mode)
{
    __shared__ float Qst[64*36];
    __shared__ float KPst[64*68];
    __shared__ float Vs[64*64];

    const int tid  = threadIdx.x;
    const int tx   = tid & 15;
    const int ty   = tid >> 4;
    const int lane = tid & 31;
    const int w    = tid >> 5;
    const int tx4  = tx * 4;
    const int ty4  = ty * 4;

    const float *qb, *gkb, *gvb, *lkb, *lvb, *mb;
    float* ctxb;
    float ps;
    int L2;

    if (mode == 0) {
        int bi = blockIdx.x;
        int qt = bi & 15; bi >>= 4;
        int n  = bi & 15; bi >>= 4;
        int h  = bi & 15;
        int b  = bi >> 4;
        size_t bh = (size_t)(b*HH + h);
        qb   = d_lq + (bh*SS + n*BLK + qt*32) * 64;
        gkb  = d_gk + bh*GG*64;
        gvb  = d_gv + bh*GG*64;
        lkb  = d_lk + (bh*SS + n*BLK) * 64;
        lvb  = d_lv + (bh*SS + n*BLK) * 64;
        mb   = mask + b*SS + n*BLK;
        ctxb = d_lctx + ((size_t)b*SS + n*BLK + qt*32) * DD + h*64;
        ps = 1.0f; L2 = BLK;
    } else {
        int bi = blockIdx.x;
        int qt = bi & 3; bi >>= 2;
        int h  = bi & 15;
        int b  = bi >> 4;
        size_t bh = (size_t)(b*HH + h);
        qb   = d_gq + (bh*GG + qt*32) * 64;
        gkb  = d_gk + bh*GG*64;
        gvb  = d_gv + bh*GG*64;
        lkb  = d_lk + bh*SS*64;
        lvb  = d_lv + bh*SS*64;
        mb   = mask + b*SS;
        ctxb = d_gctx + ((size_t)b*GG + qt*32) * DD + h*64;
        ps = 0.125f; L2 = SS;
    }

#pragma unroll
    for (int r = 0; r < 8; ++r) {
        int row = w*8 + r;
        Qst[lane*36 + row]      = qb[row*64 + lane];
        Qst[(lane+32)*36 + row] = qb[row*64 + lane + 32];
    }

    float m_r[4], l_r[4], acc[4][4];
#pragma unroll
    for (int i = 0; i < 4; ++i) {
        m_r[i] = -1e30f; l_r[i] = 0.f;
#pragma unroll
        for (int j = 0; j < 4; ++j) acc[i][j] = 0.f;
    }

    const int nch = 2 + (L2 >> 6);
    for (int c = 0; c < nch; ++c) {
        const float *kc, *vc, *mr = nullptr;
        if (c < 2) { kc = gkb + c*4096;              vc = gvb + c*4096; }
        else       { kc = lkb + (size_t)(c-2)*4096;  vc = lvb + (size_t)(c-2)*4096;
                     mr = mb + (c-2)*64; }

        __syncthreads();

#pragma unroll
        for (int r = 0; r < 16; ++r) {
            int row = w*16 + r;
            KPst[lane*68 + row]      = kc[row*64 + lane];
            KPst[(lane+32)*68 + row] = kc[row*64 + lane + 32];
        }
#pragma unroll
        for (int i = 0; i < 8; ++i)
            ((float4*)Vs)[tid + i*128] = ((const float4*)vc)[tid + i*128];

        float mk[4];
#pragma unroll
        for (int j = 0; j < 4; ++j) mk[j] = mr ? __ldg(mr + tx4 + j) : 0.f;

        __syncthreads();

        float s[4][4];
#pragma unroll
        for (int i = 0; i < 4; ++i)
#pragma unroll
            for (int j = 0; j < 4; ++j) s[i][j] = 0.f;

#pragma unroll
        for (int k = 0; k < 64; ++k) {
            float4 aq = *(const float4*)&Qst[k*36 + ty4];
            float4 bk = *(const float4*)&KPst[k*68 + tx4];
            float a_[4] = {aq.x, aq.y, aq.z, aq.w};
            float b_[4] = {bk.x, bk.y, bk.z, bk.w};
#pragma unroll
            for (int i = 0; i < 4; ++i)
#pragma unroll
                for (int j = 0; j < 4; ++j)
                    s[i][j] = fmaf(a_[i], b_[j], s[i][j]);
        }
#pragma unroll
        for (int i = 0; i < 4; ++i)
#pragma unroll
            for (int j = 0; j < 4; ++j)
                s[i][j] = s[i][j] * ps + mk[j];

#pragma unroll
        for (int i = 0; i < 4; ++i) {
            float mc = fmaxf(fmaxf(s[i][0], s[i][1]), fmaxf(s[i][2], s[i][3]));
            mc = fmaxf(mc, __shfl_xor_sync(0xffffffffu, mc, 8));
            mc = fmaxf(mc, __shfl_xor_sync(0xffffffffu, mc, 4));
            mc = fmaxf(mc, __shfl_xor_sync(0xffffffffu, mc, 2));
            mc = fmaxf(mc, __shfl_xor_sync(0xffffffffu, mc, 1));
            float mn    = fmaxf(m_r[i], mc);
            float alpha = __expf(m_r[i] - mn);
            m_r[i] = mn;
            float rs = 0.f;
#pragma unroll
            for (int j = 0; j < 4; ++j) { s[i][j] = __expf(s[i][j] - mn); rs += s[i][j]; }
            rs += __shfl_xor_sync(0xffffffffu, rs, 8);
            rs += __shfl_xor_sync(0xffffffffu, rs, 4);
            rs += __shfl_xor_sync(0xffffffffu, rs, 2);
            rs += __shfl_xor_sync(0xffffffffu, rs, 1);
            l_r[i] = l_r[i] * alpha + rs;
#pragma unroll
            for (int j = 0; j < 4; ++j) acc[i][j] *= alpha;
        }

        __syncthreads();

#pragma unroll
        for (int j = 0; j < 4; ++j) {
            float4 pv = make_float4(s[0][j], s[1][j], s[2][j], s[3][j]);
            *(float4*)&KPst[(tx4 + j)*68 + ty4] = pv;
        }
        __syncthreads();

#pragma unroll
        for (int kk = 0; kk < 64; ++kk) {
            float4 ap = *(const float4*)&KPst[kk*68 + ty4];
            float4 bv = *(const float4*)&Vs[kk*64 + tx4];
            float a_[4] = {ap.x, ap.y, ap.z, ap.w};
            float b_[4] = {bv.x, bv.y, bv.z, bv.w};
#pragma unroll
            for (int i = 0; i < 4; ++i)
#pragma unroll
                for (int j = 0; j < 4; ++j)
                    acc[i][j] = fmaf(a_[i], b_[j], acc[i][j]);
        }
    }

#pragma unroll
    for (int i = 0; i < 4; ++i) {
        float inv = 1.0f / l_r[i];
        float4 o = make_float4(acc[i][0]*inv, acc[i][1]*inv,
                               acc[i][2]*inv, acc[i][3]*inv);
        *(float4*)&ctxb[(size_t)(ty4 + i) * DD + tx4] = o;
    }
}

// ============================================================================
extern "C" void kernel_launch(void* const* d_in, const int* in_sizes, int n_in,
                              void* d_out, int out_size) {
    (void)in_sizes; (void)n_in; (void)out_size;
    const float* Q    = (const float*)d_in[0];
    const float* K    = (const float*)d_in[1];
    const float* V    = (const float*)d_in[2];
    const float* Gt   = (const float*)d_in[3];
    const float* mask = (const float*)d_in[4];
    const float* Wq = (const float*)d_in[5];
    const float* bq = (const float*)d_in[6];
    const float* Wk = (const float*)d_in[7];
    const float* bk = (const float*)d_in[8];
    const float* Wv = (const float*)d_in[9];
    const float* bv = (const float*)d_in[10];
    const float* Wo = (const float*)d_in[11];
    const float* bo = (const float*)d_in[12];
    float* out = (float*)d_out;

    void *pQ2, *pK2, *pV2, *pG2, *pC2, *pCg2, *pWq2, *pWk2, *pWv2, *pWo2, *pLc, *pGc;
    cudaGetSymbolAddress(&pQ2,  d_Q2);
    cudaGetSymbolAddress(&pK2,  d_K2);
    cudaGetSymbolAddress(&pV2,  d_V2);
    cudaGetSymbolAddress(&pG2,  d_G2);
    cudaGetSymbolAddress(&pC2,  d_C2);
    cudaGetSymbolAddress(&pCg2, d_Cg2);
    cudaGetSymbolAddress(&pWq2, d_Wq2);
    cudaGetSymbolAddress(&pWk2, d_Wk2);
    cudaGetSymbolAddress(&pWv2, d_Wv2);
    cudaGetSymbolAddress(&pWo2, d_Wo2);
    cudaGetSymbolAddress(&pLc,  d_lctx);
    cudaGetSymbolAddress(&pGc,  d_gctx);

    cudaFuncSetAttribute(gemm_tc, cudaFuncAttributeMaxDynamicSharedMemorySize, GEMM_SMEM);

    typedef const __nv_bfloat16* bfp;
    typedef __nv_bfloat16* bfpw;

    // ---- operand conversions ----
    conv_split<<<dim3(1024, 1, 4), 256>>>(Wq, Wk, Wv, Wo,
                                          (bfpw)pWq2, (bfpw)pWk2, (bfpw)pWv2, (bfpw)pWo2);
    conv_split<<<dim3(16384, 1, 3), 256>>>(Q, K, V, nullptr,
                                           (bfpw)pQ2, (bfpw)pK2, (bfpw)pV2, nullptr);
    conv_split<<<dim3(256, 1, 1), 256>>>(Gt, nullptr, nullptr, nullptr,
                                         (bfpw)pG2, nullptr, nullptr, nullptr);

    // ---- projections (tensor cores via mma.sync) ----
    gemm_tc<<<dim3(128, 8, 3), 256, GEMM_SMEM>>>(
        (bfp)pQ2, (bfp)pK2, (bfp)pV2, (bfp)pWq2, (bfp)pWk2, (bfp)pWv2,
        bq, bk, bv, 8192, 0, nullptr);
    gemm_tc<<<dim3(2, 8, 3), 256, GEMM_SMEM>>>(
        (bfp)pG2, (bfp)pG2, (bfp)pG2, (bfp)pWq2, (bfp)pWk2, (bfp)pWv2,
        bq, bk, bv, 128, 1, nullptr);

    // ---- attention (fp32) ----
    attn_kernel<<<8192, 128>>>(mask, 0);
    attn_kernel<<<128,  128>>>(mask, 1);

    // ---- context conversions + output projections ----
    conv_split<<<dim3(16384, 1, 1), 256>>>((const float*)pLc, nullptr, nullptr, nullptr,
                                           (bfpw)pC2, nullptr, nullptr, nullptr);
    conv_split<<<dim3(256, 1, 1), 256>>>((const float*)pGc, nullptr, nullptr, nullptr,
                                         (bfpw)pCg2, nullptr, nullptr, nullptr);

    gemm_tc<<<dim3(128, 8, 1), 256, GEMM_SMEM>>>(
        (bfp)pC2, nullptr, nullptr, (bfp)pWo2, nullptr, nullptr,
        bo, nullptr, nullptr, 8192, 2, out);
    gemm_tc<<<dim3(2, 8, 1), 256, GEMM_SMEM>>>(
        (bfp)pCg2, nullptr, nullptr, (bfp)pWo2, nullptr, nullptr,
        bo, nullptr, nullptr, 128, 2, out + (size_t)BB*SS*DD);
}

// round 4
// speedup vs baseline: 2.5822x; 1.3707x over previous
#include <cuda_runtime.h>
#include <cuda_bf16.h>
#include <math.h>
#include <stdint.h>

// ---------------- problem constants ----------------
#define BB   2
#define SS   8192
#define DD   1024
#define HH   16
#define GG   128

typedef __nv_bfloat16 bf16;
typedef __nv_bfloat162 bf162;

// ---------------- bf16 [hi|lo] GEMM operands ----------------
__device__ bf16 d_Q2 [(size_t)16384*2048];
__device__ bf16 d_K2 [(size_t)16384*2048];
__device__ bf16 d_V2 [(size_t)16384*2048];
__device__ bf16 d_G2 [(size_t)256*2048];
__device__ bf16 d_C2 [(size_t)16384*2048];   // attention ctx (local), hi|lo
__device__ bf16 d_Cg2[(size_t)256*2048];     // attention ctx (global), hi|lo
__device__ bf16 d_Wq2[(size_t)1024*2048];
__device__ bf16 d_Wk2[(size_t)1024*2048];
__device__ bf16 d_Wv2[(size_t)1024*2048];
__device__ bf16 d_Wo2[(size_t)1024*2048];

// head-split projected tensors, bf16, row = token, 128 cols = [hi(64)|lo(64)]
__device__ bf16 d_lq2[(size_t)BB*HH*SS*128];
__device__ bf16 d_lk2[(size_t)BB*HH*SS*128];
__device__ bf16 d_lv2[(size_t)BB*HH*SS*128];
__device__ bf16 d_gq2[(size_t)BB*HH*GG*128];
__device__ bf16 d_gk2[(size_t)BB*HH*GG*128];
__device__ bf16 d_gv2[(size_t)BB*HH*GG*128];

// ---------------- helpers ----------------
__device__ __forceinline__ uint32_t smem_u32(const void* p) {
    uint32_t a;
    asm("{ .reg .u64 t; cvta.to.shared.u64 t, %1; cvt.u32.u64 %0, t; }"
        : "=r"(a) : "l"(p));
    return a;
}
__device__ __forceinline__ void ldsm_x4(uint32_t* r, uint32_t addr) {
    asm volatile("ldmatrix.sync.aligned.m8n8.x4.shared.b16 {%0,%1,%2,%3}, [%4];"
                 : "=r"(r[0]), "=r"(r[1]), "=r"(r[2]), "=r"(r[3]) : "r"(addr));
}
__device__ __forceinline__ void ldsm_x4_t(uint32_t* r, uint32_t addr) {
    asm volatile("ldmatrix.sync.aligned.m8n8.x4.trans.shared.b16 {%0,%1,%2,%3}, [%4];"
                 : "=r"(r[0]), "=r"(r[1]), "=r"(r[2]), "=r"(r[3]) : "r"(addr));
}
__device__ __forceinline__ void mma_bf16(float* d, const uint32_t* a, const uint32_t* b) {
    asm volatile("mma.sync.aligned.m16n8k16.row.col.f32.bf16.bf16.f32 "
                 "{%0,%1,%2,%3}, {%4,%5,%6,%7}, {%8,%9}, {%0,%1,%2,%3};"
                 : "+f"(d[0]), "+f"(d[1]), "+f"(d[2]), "+f"(d[3])
                 : "r"(a[0]), "r"(a[1]), "r"(a[2]), "r"(a[3]),
                   "r"(b[0]), "r"(b[1]));
}
__device__ __forceinline__ uint32_t pack_hi(float x, float y) {
    bf162 t = __halves2bfloat162(__float2bfloat16(x), __float2bfloat16(y));
    return *(uint32_t*)&t;
}
__device__ __forceinline__ uint32_t pack_lo(float x, float y) {
    bf16 hx = __float2bfloat16(x), hy = __float2bfloat16(y);
    bf162 t = __halves2bfloat162(__float2bfloat16(x - __bfloat162float(hx)),
                                 __float2bfloat16(y - __bfloat162float(hy)));
    return *(uint32_t*)&t;
}

// ============================================================================
// conv_split: fp32 [M,1024] -> bf16 [M,2048] = [hi(1024) | lo(1024)]
// ============================================================================
__global__ void conv_split(const float* __restrict__ X0, const float* __restrict__ X1,
                           const float* __restrict__ X2, const float* __restrict__ X3,
                           bf16* __restrict__ Y0, bf16* __restrict__ Y1,
                           bf16* __restrict__ Y2, bf16* __restrict__ Y3)
{
    int z = blockIdx.z;
    const float* X = (z==0)?X0:(z==1)?X1:(z==2)?X2:X3;
    bf16* Y = (z==0)?Y0:(z==1)?Y1:(z==2)?Y2:Y3;
    size_t row = blockIdx.x;
    int col = threadIdx.x * 4;
    float4 x = *(const float4*)(X + row*1024 + col);
    bf162* ph = (bf162*)(Y + row*2048 + col);
    bf162* pl = (bf162*)(Y + row*2048 + 1024 + col);
    ph[0] = __halves2bfloat162(__float2bfloat16(x.x), __float2bfloat16(x.y));
    ph[1] = __halves2bfloat162(__float2bfloat16(x.z), __float2bfloat16(x.w));
    pl[0] = *(bf162*)&(uint32_t&)*(uint32_t*)&ph[0]; // placeholder, overwritten below
    // compute lo properly
    bf16 h0 = __float2bfloat16(x.x), h1 = __float2bfloat16(x.y);
    bf16 h2 = __float2bfloat16(x.z), h3 = __float2bfloat16(x.w);
    pl[0] = __halves2bfloat162(__float2bfloat16(x.x - __bfloat162float(h0)),
                               __float2bfloat16(x.y - __bfloat162float(h1)));
    pl[1] = __halves2bfloat162(__float2bfloat16(x.z - __bfloat162float(h2)),
                               __float2bfloat16(x.w - __bfloat162float(h3)));
}

// ============================================================================
// gemm_tc: C = (A . W^T + bias) * scale via bf16x3 on mma.sync.
// grid.x = nbig + nsmall; blocks >= nbig use Ag (appended small-M region).
// mode 0: epilogue -> head-split bf16 hi|lo (big: lq2/lk2/lv2 by z,
//         small: gq2/gk2/gv2); scale 0.125 on z==0.
// mode 2: epilogue -> fp32 outp rows (big at 0, small at 16384).
// ============================================================================
#define NST  3
#define STB  32768
#define NCH  48
#define GEMM_SMEM (NST*STB)

__global__ void __launch_bounds__(256) gemm_tc(
    const bf16* __restrict__ A0, const bf16* __restrict__ A1,
    const bf16* __restrict__ A2, const bf16* __restrict__ Ag,
    const bf16* __restrict__ W0, const bf16* __restrict__ W1,
    const bf16* __restrict__ W2,
    const float* __restrict__ Bi0, const float* __restrict__ Bi1,
    const float* __restrict__ Bi2,
    int nbig, int mode, float* __restrict__ outp)
{
    extern __shared__ char smem[];
    const uint32_t sb  = smem_u32(smem);
    const int tid  = threadIdx.x;
    const int wid  = tid >> 5;
    const int lane = tid & 31;
    const int z    = blockIdx.z;
    const int bx   = blockIdx.x;
    const bool big = bx < nbig;

    const bf16* A = big ? ((z==0)?A0:(z==1)?A1:A2) : Ag;
    const bf16* W = (z==0)?W0:(z==1)?W1:W2;
    const float* bias = (z==0)?Bi0:(z==1)?Bi1:Bi2;

    const int m0 = (big ? bx : bx - nbig) * 128;
    const int n0 = blockIdx.y * 128;
    const float scale = (mode == 0 && z == 0) ? 0.125f : 1.0f;

    const int      r0  = tid >> 3;
    const int      c16 = tid & 7;
    const uint32_t swo = (uint32_t)(tid*16) ^ ((uint32_t)(tid*2) & 0x70);
    const bf16* Abase = A + (size_t)(m0 + r0)*2048 + c16*8;
    const bf16* Wbase = W + (size_t)(n0 + r0)*2048 + c16*8;

    auto load_stage = [&](int stage, int c) {
        const int aIdx = (c < 16) ? c : c - 16;   // A: hi,hi,lo
        const int wIdx = (c < 32) ? c : c - 32;   // W: hi,lo,hi
        const bf16* ga = Abase + aIdx*64;
        const bf16* gw = Wbase + wIdx*64;
        const uint32_t smA = sb + stage*STB;
        const uint32_t smB = smA + 16384;
#pragma unroll
        for (int i = 0; i < 4; ++i)
            asm volatile("cp.async.cg.shared.global [%0], [%1], 16;"
                         :: "r"(smA + swo + i*4096), "l"(ga + (size_t)i*32*2048));
#pragma unroll
        for (int i = 0; i < 4; ++i)
            asm volatile("cp.async.cg.shared.global [%0], [%1], 16;"
                         :: "r"(smB + swo + i*4096), "l"(gw + (size_t)i*32*2048));
        asm volatile("cp.async.commit_group;" ::: "memory");
    };

    const int wr = wid & 3;
    const int wc = wid >> 2;
    const int arow = wr*32 + (lane & 15);
    const int akb  = lane >> 4;
    const int g    = lane >> 3;
    const int brow = wc*64 + (g >> 1)*8 + (lane & 7);
    const int bkb  = g & 1;

    float acc[2][8][4];
#pragma unroll
    for (int t = 0; t < 2; ++t)
#pragma unroll
        for (int j = 0; j < 8; ++j)
#pragma unroll
            for (int e = 0; e < 4; ++e) acc[t][j][e] = 0.f;

    load_stage(0, 0);
    load_stage(1, 1);

    for (int c = 0; c < NCH; ++c) {
        if (c < NCH-1) asm volatile("cp.async.wait_group 1;" ::: "memory");
        else           asm volatile("cp.async.wait_group 0;" ::: "memory");
        __syncthreads();
        if (c + 2 < NCH) load_stage((c+2) % NST, c+2);

        const uint32_t smA = sb + (c % NST)*STB;
        const uint32_t smB = smA + 16384;

#pragma unroll
        for (int ks = 0; ks < 4; ++ks) {
            const int kb = ks*2;
            uint32_t af[2][4];
#pragma unroll
            for (int t = 0; t < 2; ++t) {
                int row = arow + t*16;
                uint32_t off = (uint32_t)(row*128 + (kb + akb)*16);
                ldsm_x4(af[t], smA + (off ^ ((row & 7) * 16)));
            }
            uint32_t bf[4][4];
#pragma unroll
            for (int u = 0; u < 4; ++u) {
                int row = brow + u*16;
                uint32_t off = (uint32_t)(row*128 + (kb + bkb)*16);
                ldsm_x4(bf[u], smB + (off ^ ((row & 7) * 16)));
            }
#pragma unroll
            for (int t = 0; t < 2; ++t)
#pragma unroll
                for (int j = 0; j < 8; ++j)
                    mma_bf16(acc[t][j], af[t], &bf[j>>1][(j&1)*2]);
        }
    }
    __syncthreads();

    // ---- epilogue ----
#pragma unroll
    for (int t = 0; t < 2; ++t) {
        const int r1 = m0 + wr*32 + t*16 + (lane >> 2);
        const int r2 = r1 + 8;
#pragma unroll
        for (int j = 0; j < 8; ++j) {
            const int nb = n0 + wc*64 + j*8 + (lane & 3)*2;
            float2 bv = *(const float2*)(bias + nb);
            float2 v1, v2;
            v1.x = (acc[t][j][0] + bv.x) * scale;
            v1.y = (acc[t][j][1] + bv.y) * scale;
            v2.x = (acc[t][j][2] + bv.x) * scale;
            v2.y = (acc[t][j][3] + bv.y) * scale;
            if (mode == 2) {
                const size_t ro = big ? 0 : 16384;
                *(float2*)(outp + (ro + r1) * 1024 + nb) = v1;
                *(float2*)(outp + (ro + r2) * 1024 + nb) = v2;
            } else {
                bf16* T = big ? ((z==0)?d_lq2:(z==1)?d_lk2:d_lv2)
                              : ((z==0)?d_gq2:(z==1)?d_gk2:d_gv2);
                const int Lr = big ? SS : GG;
                const int h = nb >> 6;
                const int f = nb & 63;
                {
                    int b = r1 / Lr, s = r1 - b*Lr;
                    bf16* base = T + ((size_t)(b*HH + h)*Lr + s)*128 + f;
                    *(bf162*)base      = __halves2bfloat162(__float2bfloat16(v1.x),
                                                            __float2bfloat16(v1.y));
                    uint32_t pl = pack_lo(v1.x, v1.y);
                    *(uint32_t*)(base + 64) = pl;
                }
                {
                    int b = r2 / Lr, s = r2 - b*Lr;
                    bf16* base = T + ((size_t)(b*HH + h)*Lr + s)*128 + f;
                    *(bf162*)base      = __halves2bfloat162(__float2bfloat16(v2.x),
                                                            __float2bfloat16(v2.y));
                    uint32_t pl = pack_lo(v2.x, v2.y);
                    *(uint32_t*)(base + 64) = pl;
                }
            }
        }
    }
}

// ============================================================================
// attn_tc: flash attention on tensor cores (bf16x3 splits everywhere).
// CTA = 64 q rows (4 warps x m16), key chunks of 64, 3-stage cp.async.
// smem tile format: 128 rows x 128B; rows 0-63 = hi part, 64-127 = lo part.
// mode 0: local block attention  (grid 4096)
// mode 1: global attention       (grid 64)
// ============================================================================
#define ASTB 32768
#define ATT_SMEM (3*ASTB)

__global__ void __launch_bounds__(128) attn_tc(const float* __restrict__ mask, int mode)
{
    extern __shared__ char smem[];
    const uint32_t sb = smem_u32(smem);
    const int tid  = threadIdx.x;
    const int lane = tid & 31;
    const int w    = tid >> 5;

    const bf16 *qb, *kg, *vg, *kl, *vl;
    const float* mrow;
    bf16* outC;
    size_t outrow0;
    float ps;
    int nch;

    if (mode == 0) {
        int bi = blockIdx.x;
        int qt = bi & 7;  bi >>= 3;
        int n  = bi & 15; bi >>= 4;
        int h  = bi & 15;
        int b  = bi >> 4;
        size_t bh = (size_t)(b*HH + h);
        qb = d_lq2 + (bh*SS + n*512 + qt*64)*128;
        kg = d_gk2 + bh*GG*128;
        vg = d_gv2 + bh*GG*128;
        kl = d_lk2 + (bh*SS + n*512)*128;
        vl = d_lv2 + (bh*SS + n*512)*128;
        mrow = mask + b*SS + n*512;
        outC = d_C2 + (size_t)(h*64);
        outrow0 = (size_t)b*SS + n*512 + qt*64;
        ps = 1.0f; nch = 10;
    } else {
        int bi = blockIdx.x;
        int qt = bi & 1;  bi >>= 1;
        int h  = bi & 15;
        int b  = bi >> 4;
        size_t bh = (size_t)(b*HH + h);
        qb = d_gq2 + (bh*GG + qt*64)*128;
        kg = d_gk2 + bh*GG*128;
        vg = d_gv2 + bh*GG*128;
        kl = d_lk2 + bh*SS*128;
        vl = d_lv2 + bh*SS*128;
        mrow = mask + b*SS;
        outC = d_Cg2 + (size_t)(h*64);
        outrow0 = (size_t)b*GG + qt*64;
        ps = 0.125f; nch = 130;
    }

    // ---- stage Q into buffer 0, ldmatrix to registers ----
    {
        int r = tid;
        const bf16* src = qb + (r & 63)*128 + (r >> 6)*64;
        uint32_t dst = sb + r*128;
#pragma unroll
        for (int u = 0; u < 8; ++u)
            asm volatile("cp.async.cg.shared.global [%0], [%1], 16;"
                         :: "r"(dst + ((u*16) ^ ((r & 7)*16))), "l"(src + u*8));
        asm volatile("cp.async.commit_group;" ::: "memory");
        asm volatile("cp.async.wait_group 0;" ::: "memory");
        __syncthreads();
    }
    uint32_t qh[4][4], ql[4][4];
    {
        const int arow = w*16 + (lane & 15);
        const int akb  = lane >> 4;
#pragma unroll
        for (int ks = 0; ks < 4; ++ks) {
            uint32_t off = (uint32_t)((ks*2 + akb)*16);
            ldsm_x4(qh[ks], sb + arow*128       + (off ^ ((arow & 7)*16)));
            int arl = arow + 64;
            ldsm_x4(ql[ks], sb + arl*128        + (off ^ ((arl & 7)*16)));
        }
    }
    __syncthreads();

    // ---- pipeline K/V chunks ----
    auto load_chunk = [&](int c, int stage) {
        const bf16 *ksrc, *vsrc;
        if (c < 2) { ksrc = kg + (size_t)c*64*128;     vsrc = vg + (size_t)c*64*128; }
        else       { ksrc = kl + (size_t)(c-2)*64*128; vsrc = vl + (size_t)(c-2)*64*128; }
        int r = tid;
        const bf16* sk = ksrc + (r & 63)*128 + (r >> 6)*64;
        const bf16* sv = vsrc + (r & 63)*128 + (r >> 6)*64;
        uint32_t dK = sb + stage*ASTB + r*128;
        uint32_t dV = dK + 16384;
#pragma unroll
        for (int u = 0; u < 8; ++u)
            asm volatile("cp.async.cg.shared.global [%0], [%1], 16;"
                         :: "r"(dK + ((u*16) ^ ((r & 7)*16))), "l"(sk + u*8));
#pragma unroll
        for (int u = 0; u < 8; ++u)
            asm volatile("cp.async.cg.shared.global [%0], [%1], 16;"
                         :: "r"(dV + ((u*16) ^ ((r & 7)*16))), "l"(sv + u*8));
        asm volatile("cp.async.commit_group;" ::: "memory");
    };

    load_chunk(0, 0);
    load_chunk(1, 1);

    float m0r = -1e30f, m1r = -1e30f, l0r = 0.f, l1r = 0.f;
    float oacc[8][4];
#pragma unroll
    for (int j = 0; j < 8; ++j)
#pragma unroll
        for (int e = 0; e < 4; ++e) oacc[j][e] = 0.f;

    const int g     = lane >> 3;
    const int brow0 = (g >> 1)*8 + (lane & 7);
    const int bkb   = g & 1;
    const int vrow0 = (g & 1)*8 + (lane & 7);
    const int vcol  = (g >> 1)*16;     // bytes within dim segment

    for (int c = 0; c < nch; ++c) {
        if (c < nch-1) asm volatile("cp.async.wait_group 1;" ::: "memory");
        else           asm volatile("cp.async.wait_group 0;" ::: "memory");
        __syncthreads();
        if (c + 2 < nch) load_chunk(c+2, (c+2) % 3);

        const uint32_t Kb = sb + (c % 3)*ASTB;
        const uint32_t Vb = Kb + 16384;

        // ---- scores (Qhi.Khi + Qlo.Khi + Qhi.Klo) ----
        float sacc[8][4];
#pragma unroll
        for (int j = 0; j < 8; ++j)
#pragma unroll
            for (int e = 0; e < 4; ++e) sacc[j][e] = 0.f;

#pragma unroll
        for (int ks = 0; ks < 4; ++ks) {
            uint32_t bfh[4][4];
#pragma unroll
            for (int u = 0; u < 4; ++u) {
                int row = brow0 + u*16;
                uint32_t off = (uint32_t)((ks*2 + bkb)*16);
                ldsm_x4(bfh[u], Kb + row*128 + (off ^ ((row & 7)*16)));
            }
#pragma unroll
            for (int j = 0; j < 8; ++j) {
                mma_bf16(sacc[j], qh[ks], &bfh[j>>1][(j&1)*2]);
                mma_bf16(sacc[j], ql[ks], &bfh[j>>1][(j&1)*2]);
            }
            uint32_t bfl[4][4];
#pragma unroll
            for (int u = 0; u < 4; ++u) {
                int row = brow0 + u*16 + 64;
                uint32_t off = (uint32_t)((ks*2 + bkb)*16);
                ldsm_x4(bfl[u], Kb + row*128 + (off ^ ((row & 7)*16)));
            }
#pragma unroll
            for (int j = 0; j < 8; ++j)
                mma_bf16(sacc[j], qh[ks], &bfl[j>>1][(j&1)*2]);
        }

        // ---- mask + online softmax ----
        float mx0 = -1e30f, mx1 = -1e30f;
        const int kb0 = (c - 2)*64 + (lane & 3)*2;
#pragma unroll
        for (int j = 0; j < 8; ++j) {
            float mkx = 0.f, mky = 0.f;
            if (c >= 2) {
                float2 mm = __ldg((const float2*)(mrow + kb0 + j*8));
                mkx = mm.x; mky = mm.y;
            }
            sacc[j][0] = fmaf(sacc[j][0], ps, mkx);
            sacc[j][1] = fmaf(sacc[j][1], ps, mky);
            sacc[j][2] = fmaf(sacc[j][2], ps, mkx);
            sacc[j][3] = fmaf(sacc[j][3], ps, mky);
            mx0 = fmaxf(mx0, fmaxf(sacc[j][0], sacc[j][1]));
            mx1 = fmaxf(mx1, fmaxf(sacc[j][2], sacc[j][3]));
        }
        mx0 = fmaxf(mx0, __shfl_xor_sync(0xffffffffu, mx0, 1));
        mx0 = fmaxf(mx0, __shfl_xor_sync(0xffffffffu, mx0, 2));
        mx1 = fmaxf(mx1, __shfl_xor_sync(0xffffffffu, mx1, 1));
        mx1 = fmaxf(mx1, __shfl_xor_sync(0xffffffffu, mx1, 2));

        float mn0 = fmaxf(m0r, mx0), mn1 = fmaxf(m1r, mx1);
        float a0 = __expf(m0r - mn0), a1 = __expf(m1r - mn1);
        m0r = mn0; m1r = mn1;

        float sum0 = 0.f, sum1 = 0.f;
#pragma unroll
        for (int j = 0; j < 8; ++j) {
            sacc[j][0] = __expf(sacc[j][0] - mn0);
            sacc[j][1] = __expf(sacc[j][1] - mn0);
            sacc[j][2] = __expf(sacc[j][2] - mn1);
            sacc[j][3] = __expf(sacc[j][3] - mn1);
            sum0 += sacc[j][0] + sacc[j][1];
            sum1 += sacc[j][2] + sacc[j][3];
        }
        sum0 += __shfl_xor_sync(0xffffffffu, sum0, 1);
        sum0 += __shfl_xor_sync(0xffffffffu, sum0, 2);
        sum1 += __shfl_xor_sync(0xffffffffu, sum1, 1);
        sum1 += __shfl_xor_sync(0xffffffffu, sum1, 2);
        l0r = l0r*a0 + sum0;
        l1r = l1r*a1 + sum1;
#pragma unroll
        for (int j = 0; j < 8; ++j) {
            oacc[j][0] *= a0; oacc[j][1] *= a0;
            oacc[j][2] *= a1; oacc[j][3] *= a1;
        }

        // ---- P fragments (register-local hi/lo split) + PV ----
#pragma unroll
        for (int kv = 0; kv < 4; ++kv) {
            uint32_t pah[4], pal[4];
            pah[0] = pack_hi(sacc[2*kv][0],   sacc[2*kv][1]);
            pah[1] = pack_hi(sacc[2*kv][2],   sacc[2*kv][3]);
            pah[2] = pack_hi(sacc[2*kv+1][0], sacc[2*kv+1][1]);
            pah[3] = pack_hi(sacc[2*kv+1][2], sacc[2*kv+1][3]);
            pal[0] = pack_lo(sacc[2*kv][0],   sacc[2*kv][1]);
            pal[1] = pack_lo(sacc[2*kv][2],   sacc[2*kv][3]);
            pal[2] = pack_lo(sacc[2*kv+1][0], sacc[2*kv+1][1]);
            pal[3] = pack_lo(sacc[2*kv+1][2], sacc[2*kv+1][3]);

            uint32_t vfh[4][4];
#pragma unroll
            for (int dg = 0; dg < 4; ++dg) {
                int row = kv*16 + vrow0;
                uint32_t off = (uint32_t)(dg*32 + vcol);
                ldsm_x4_t(vfh[dg], Vb + row*128 + (off ^ ((row & 7)*16)));
            }
#pragma unroll
            for (int j = 0; j < 8; ++j) {
                mma_bf16(oacc[j], pah, &vfh[j>>1][(j&1)*2]);
                mma_bf16(oacc[j], pal, &vfh[j>>1][(j&1)*2]);
            }
            uint32_t vfl[4][4];
#pragma unroll
            for (int dg = 0; dg < 4; ++dg) {
                int row = kv*16 + vrow0 + 64;
                uint32_t off = (uint32_t)(dg*32 + vcol);
                ldsm_x4_t(vfl[dg], Vb + row*128 + (off ^ ((row & 7)*16)));
            }
#pragma unroll
            for (int j = 0; j < 8; ++j)
                mma_bf16(oacc[j], pah, &vfl[j>>1][(j&1)*2]);
        }
    }

    // ---- epilogue: normalize, hi/lo split, write ctx ----
    const float inv0 = 1.0f / l0r;
    const float inv1 = 1.0f / l1r;
    const size_t row0 = outrow0 + w*16 + (lane >> 2);
    const size_t row1 = row0 + 8;
#pragma unroll
    for (int j = 0; j < 8; ++j) {
        const int col = j*8 + (lane & 3)*2;
        float x0 = oacc[j][0]*inv0, y0 = oacc[j][1]*inv0;
        float x1 = oacc[j][2]*inv1, y1 = oacc[j][3]*inv1;
        bf16* p0 = outC + row0*2048 + col;
        bf16* p1 = outC + row1*2048 + col;
        *(uint32_t*)p0          = pack_hi(x0, y0);
        *(uint32_t*)(p0 + 1024) = pack_lo(x0, y0);
        *(uint32_t*)p1          = pack_hi(x1, y1);
        *(uint32_t*)(p1 + 1024) = pack_lo(x1, y1);
    }
}

// ============================================================================
extern "C" void kernel_launch(void* const* d_in, const int* in_sizes, int n_in,
                              void* d_out, int out_size) {
    (void)in_sizes; (void)n_in; (void)out_size;
    const float* Q    = (const float*)d_in[0];
    const float* K    = (const float*)d_in[1];
    const float* V    = (const float*)d_in[2];
    const float* Gt   = (const float*)d_in[3];
    const float* mask = (const float*)d_in[4];
    const float* Wq = (const float*)d_in[5];
    const float* bq = (const float*)d_in[6];
    const float* Wk = (const float*)d_in[7];
    const float* bk = (const float*)d_in[8];
    const float* Wv = (const float*)d_in[9];
    const float* bv = (const float*)d_in[10];
    const float* Wo = (const float*)d_in[11];
    const float* bo = (const float*)d_in[12];
    float* out = (float*)d_out;

    void *pQ2, *pK2, *pV2, *pG2, *pC2, *pCg2, *pWq2, *pWk2, *pWv2, *pWo2;
    cudaGetSymbolAddress(&pQ2,  d_Q2);
    cudaGetSymbolAddress(&pK2,  d_K2);
    cudaGetSymbolAddress(&pV2,  d_V2);
    cudaGetSymbolAddress(&pG2,  d_G2);
    cudaGetSymbolAddress(&pC2,  d_C2);
    cudaGetSymbolAddress(&pCg2, d_Cg2);
    cudaGetSymbolAddress(&pWq2, d_Wq2);
    cudaGetSymbolAddress(&pWk2, d_Wk2);
    cudaGetSymbolAddress(&pWv2, d_Wv2);
    cudaGetSymbolAddress(&pWo2, d_Wo2);

    cudaFuncSetAttribute(gemm_tc, cudaFuncAttributeMaxDynamicSharedMemorySize, GEMM_SMEM);
    cudaFuncSetAttribute(attn_tc, cudaFuncAttributeMaxDynamicSharedMemorySize, ATT_SMEM);

    typedef const bf16* bfp;
    typedef bf16* bfpw;

    // operand conversions
    conv_split<<<dim3(1024, 1, 4), 256>>>(Wq, Wk, Wv, Wo,
                                          (bfpw)pWq2, (bfpw)pWk2, (bfpw)pWv2, (bfpw)pWo2);
    conv_split<<<dim3(16384, 1, 3), 256>>>(Q, K, V, nullptr,
                                           (bfpw)pQ2, (bfpw)pK2, (bfpw)pV2, nullptr);
    conv_split<<<dim3(256, 1, 1), 256>>>(Gt, nullptr, nullptr, nullptr,
                                         (bfpw)pG2, nullptr, nullptr, nullptr);

    // projections (big + appended global rows), head-split bf16 hi|lo out
    gemm_tc<<<dim3(130, 8, 3), 256, GEMM_SMEM>>>(
        (bfp)pQ2, (bfp)pK2, (bfp)pV2, (bfp)pG2,
        (bfp)pWq2, (bfp)pWk2, (bfp)pWv2,
        bq, bk, bv, 128, 0, nullptr);

    // attention (tensor cores)
    attn_tc<<<4096, 128, ATT_SMEM>>>(mask, 0);
    attn_tc<<<64,   128, ATT_SMEM>>>(mask, 1);

    // output projection (big ctx + appended global ctx) -> fp32 out
    gemm_tc<<<dim3(130, 8, 1), 256, GEMM_SMEM>>>(
        (bfp)pC2, nullptr, nullptr, (bfp)pCg2,
        (bfp)pWo2, nullptr, nullptr,
        bo, nullptr, nullptr, 128, 2, out);
}

// round 5
// speedup vs baseline: 3.2853x; 1.2723x over previous
#include <cuda_runtime.h>
#include <cuda_bf16.h>
#include <math.h>
#include <stdint.h>

// ---------------- problem constants ----------------
#define BB   2
#define SS   8192
#define DD   1024
#define HH   16
#define GG   128

typedef __nv_bfloat16 bf16;
typedef __nv_bfloat162 bf162;

// ---------------- bf16 [hi|lo] GEMM operands ----------------
__device__ bf16 d_Q2 [(size_t)16384*2048];
__device__ bf16 d_K2 [(size_t)16384*2048];
__device__ bf16 d_V2 [(size_t)16384*2048];
__device__ bf16 d_G2 [(size_t)256*2048];
__device__ bf16 d_C2 [(size_t)16384*2048];   // attention ctx (local), hi|lo
__device__ bf16 d_Cg2[(size_t)256*2048];     // attention ctx (global), hi|lo
__device__ bf16 d_Wq2[(size_t)1024*2048];
__device__ bf16 d_Wk2[(size_t)1024*2048];
__device__ bf16 d_Wv2[(size_t)1024*2048];
__device__ bf16 d_Wo2[(size_t)1024*2048];

// head-split projected tensors, bf16, row = token, 128 cols = [hi(64)|lo(64)]
__device__ bf16 d_lq2[(size_t)BB*HH*SS*128];
__device__ bf16 d_lk2[(size_t)BB*HH*SS*128];
__device__ bf16 d_lv2[(size_t)BB*HH*SS*128];
__device__ bf16 d_gq2[(size_t)BB*HH*GG*128];
__device__ bf16 d_gk2[(size_t)BB*HH*GG*128];
__device__ bf16 d_gv2[(size_t)BB*HH*GG*128];

// ---------------- helpers ----------------
__device__ __forceinline__ uint32_t smem_u32(const void* p) {
    uint32_t a;
    asm("{ .reg .u64 t; cvta.to.shared.u64 t, %1; cvt.u32.u64 %0, t; }"
        : "=r"(a) : "l"(p));
    return a;
}
__device__ __forceinline__ void ldsm_x4(uint32_t* r, uint32_t addr) {
    asm volatile("ldmatrix.sync.aligned.m8n8.x4.shared.b16 {%0,%1,%2,%3}, [%4];"
                 : "=r"(r[0]), "=r"(r[1]), "=r"(r[2]), "=r"(r[3]) : "r"(addr));
}
__device__ __forceinline__ void ldsm_x4_t(uint32_t* r, uint32_t addr) {
    asm volatile("ldmatrix.sync.aligned.m8n8.x4.trans.shared.b16 {%0,%1,%2,%3}, [%4];"
                 : "=r"(r[0]), "=r"(r[1]), "=r"(r[2]), "=r"(r[3]) : "r"(addr));
}
__device__ __forceinline__ void mma_bf16(float* d, const uint32_t* a, const uint32_t* b) {
    asm volatile("mma.sync.aligned.m16n8k16.row.col.f32.bf16.bf16.f32 "
                 "{%0,%1,%2,%3}, {%4,%5,%6,%7}, {%8,%9}, {%0,%1,%2,%3};"
                 : "+f"(d[0]), "+f"(d[1]), "+f"(d[2]), "+f"(d[3])
                 : "r"(a[0]), "r"(a[1]), "r"(a[2]), "r"(a[3]),
                   "r"(b[0]), "r"(b[1]));
}
__device__ __forceinline__ uint32_t pack_hi(float x, float y) {
    bf162 t = __halves2bfloat162(__float2bfloat16(x), __float2bfloat16(y));
    return *(uint32_t*)&t;
}
__device__ __forceinline__ uint32_t pack_lo(float x, float y) {
    bf16 hx = __float2bfloat16(x), hy = __float2bfloat16(y);
    bf162 t = __halves2bfloat162(__float2bfloat16(x - __bfloat162float(hx)),
                                 __float2bfloat16(y - __bfloat162float(hy)));
    return *(uint32_t*)&t;
}

// ============================================================================
// conv_split: fp32 [M,1024] -> bf16 [M,2048] = [hi(1024) | lo(1024)]
// ============================================================================
__global__ void conv_split(const float* __restrict__ X0, const float* __restrict__ X1,
                           const float* __restrict__ X2, const float* __restrict__ X3,
                           bf16* __restrict__ Y0, bf16* __restrict__ Y1,
                           bf16* __restrict__ Y2, bf16* __restrict__ Y3)
{
    int z = blockIdx.z;
    const float* X = (z==0)?X0:(z==1)?X1:(z==2)?X2:X3;
    bf16* Y = (z==0)?Y0:(z==1)?Y1:(z==2)?Y2:Y3;
    size_t row = blockIdx.x;
    int col = threadIdx.x * 4;
    float4 x = *(const float4*)(X + row*1024 + col);
    bf16 h0 = __float2bfloat16(x.x), h1 = __float2bfloat16(x.y);
    bf16 h2 = __float2bfloat16(x.z), h3 = __float2bfloat16(x.w);
    bf162* ph = (bf162*)(Y + row*2048 + col);
    bf162* pl = (bf162*)(Y + row*2048 + 1024 + col);
    ph[0] = __halves2bfloat162(h0, h1);
    ph[1] = __halves2bfloat162(h2, h3);
    pl[0] = __halves2bfloat162(__float2bfloat16(x.x - __bfloat162float(h0)),
                               __float2bfloat16(x.y - __bfloat162float(h1)));
    pl[1] = __halves2bfloat162(__float2bfloat16(x.z - __bfloat162float(h2)),
                               __float2bfloat16(x.w - __bfloat162float(h3)));
}

// ============================================================================
// gemm_tc: C = (A . W^T + bias) * scale via bf16x3 on mma.sync.
// grid.x = nbig + nsmall; blocks >= nbig use Ag (appended small-M region).
// mode 0: epilogue -> head-split bf16 hi|lo; mode 2: fp32 outp.
// __launch_bounds__(256,2): cap regs at 128 so 2 CTAs/SM fit (Round-4 fix).
// ============================================================================
#define NST  3
#define STB  32768
#define NCH  48
#define GEMM_SMEM (NST*STB)

__global__ void __launch_bounds__(256, 2) gemm_tc(
    const bf16* __restrict__ A0, const bf16* __restrict__ A1,
    const bf16* __restrict__ A2, const bf16* __restrict__ Ag,
    const bf16* __restrict__ W0, const bf16* __restrict__ W1,
    const bf16* __restrict__ W2,
    const float* __restrict__ Bi0, const float* __restrict__ Bi1,
    const float* __restrict__ Bi2,
    int nbig, int mode, float* __restrict__ outp)
{
    extern __shared__ char smem[];
    const uint32_t sb  = smem_u32(smem);
    const int tid  = threadIdx.x;
    const int wid  = tid >> 5;
    const int lane = tid & 31;
    const int z    = blockIdx.z;
    const int bx   = blockIdx.x;
    const bool big = bx < nbig;

    const bf16* A = big ? ((z==0)?A0:(z==1)?A1:A2) : Ag;
    const bf16* W = (z==0)?W0:(z==1)?W1:W2;
    const float* bias = (z==0)?Bi0:(z==1)?Bi1:Bi2;

    const int m0 = (big ? bx : bx - nbig) * 128;
    const int n0 = blockIdx.y * 128;
    const float scale = (mode == 0 && z == 0) ? 0.125f : 1.0f;

    const int      r0  = tid >> 3;
    const int      c16 = tid & 7;
    const uint32_t swo = (uint32_t)(tid*16) ^ ((uint32_t)(tid*2) & 0x70);
    const bf16* Abase = A + (size_t)(m0 + r0)*2048 + c16*8;
    const bf16* Wbase = W + (size_t)(n0 + r0)*2048 + c16*8;

    auto load_stage = [&](int stage, int c) {
        const int aIdx = (c < 16) ? c : c - 16;   // A: hi,hi,lo
        const int wIdx = (c < 32) ? c : c - 32;   // W: hi,lo,hi
        const bf16* ga = Abase + aIdx*64;
        const bf16* gw = Wbase + wIdx*64;
        const uint32_t smA = sb + stage*STB;
        const uint32_t smB = smA + 16384;
#pragma unroll
        for (int i = 0; i < 4; ++i)
            asm volatile("cp.async.cg.shared.global [%0], [%1], 16;"
                         :: "r"(smA + swo + i*4096), "l"(ga + (size_t)i*32*2048));
#pragma unroll
        for (int i = 0; i < 4; ++i)
            asm volatile("cp.async.cg.shared.global [%0], [%1], 16;"
                         :: "r"(smB + swo + i*4096), "l"(gw + (size_t)i*32*2048));
        asm volatile("cp.async.commit_group;" ::: "memory");
    };

    const int wr = wid & 3;
    const int wc = wid >> 2;
    const int arow = wr*32 + (lane & 15);
    const int akb  = lane >> 4;
    const int g    = lane >> 3;
    const int brow = wc*64 + (g >> 1)*8 + (lane & 7);
    const int bkb  = g & 1;

    float acc[2][8][4];
#pragma unroll
    for (int t = 0; t < 2; ++t)
#pragma unroll
        for (int j = 0; j < 8; ++j)
#pragma unroll
            for (int e = 0; e < 4; ++e) acc[t][j][e] = 0.f;

    load_stage(0, 0);
    load_stage(1, 1);

    for (int c = 0; c < NCH; ++c) {
        if (c < NCH-1) asm volatile("cp.async.wait_group 1;" ::: "memory");
        else           asm volatile("cp.async.wait_group 0;" ::: "memory");
        __syncthreads();
        if (c + 2 < NCH) load_stage((c+2) % NST, c+2);

        const uint32_t smA = sb + (c % NST)*STB;
        const uint32_t smB = smA + 16384;

#pragma unroll
        for (int ks = 0; ks < 4; ++ks) {
            const int kb = ks*2;
            uint32_t af[2][4];
#pragma unroll
            for (int t = 0; t < 2; ++t) {
                int row = arow + t*16;
                uint32_t off = (uint32_t)(row*128 + (kb + akb)*16);
                ldsm_x4(af[t], smA + (off ^ ((row & 7) * 16)));
            }
            uint32_t bf[4][4];
#pragma unroll
            for (int u = 0; u < 4; ++u) {
                int row = brow + u*16;
                uint32_t off = (uint32_t)(row*128 + (kb + bkb)*16);
                ldsm_x4(bf[u], smB + (off ^ ((row & 7) * 16)));
            }
#pragma unroll
            for (int t = 0; t < 2; ++t)
#pragma unroll
                for (int j = 0; j < 8; ++j)
                    mma_bf16(acc[t][j], af[t], &bf[j>>1][(j&1)*2]);
        }
    }
    __syncthreads();

    // ---- epilogue ----
#pragma unroll
    for (int t = 0; t < 2; ++t) {
        const int r1 = m0 + wr*32 + t*16 + (lane >> 2);
        const int r2 = r1 + 8;
#pragma unroll
        for (int j = 0; j < 8; ++j) {
            const int nb = n0 + wc*64 + j*8 + (lane & 3)*2;
            float2 bv = *(const float2*)(bias + nb);
            float2 v1, v2;
            v1.x = (acc[t][j][0] + bv.x) * scale;
            v1.y = (acc[t][j][1] + bv.y) * scale;
            v2.x = (acc[t][j][2] + bv.x) * scale;
            v2.y = (acc[t][j][3] + bv.y) * scale;
            if (mode == 2) {
                const size_t ro = big ? 0 : 16384;
                *(float2*)(outp + (ro + r1) * 1024 + nb) = v1;
                *(float2*)(outp + (ro + r2) * 1024 + nb) = v2;
            } else {
                bf16* T = big ? ((z==0)?d_lq2:(z==1)?d_lk2:d_lv2)
                              : ((z==0)?d_gq2:(z==1)?d_gk2:d_gv2);
                const int Lr = big ? SS : GG;
                const int h = nb >> 6;
                const int f = nb & 63;
                {
                    int b = r1 / Lr, s = r1 - b*Lr;
                    bf16* base = T + ((size_t)(b*HH + h)*Lr + s)*128 + f;
                    *(uint32_t*)base        = pack_hi(v1.x, v1.y);
                    *(uint32_t*)(base + 64) = pack_lo(v1.x, v1.y);
                }
                {
                    int b = r2 / Lr, s = r2 - b*Lr;
                    bf16* base = T + ((size_t)(b*HH + h)*Lr + s)*128 + f;
                    *(uint32_t*)base        = pack_hi(v2.x, v2.y);
                    *(uint32_t*)(base + 64) = pack_lo(v2.x, v2.y);
                }
            }
        }
    }
}

// ============================================================================
// attn_tc: flash attention on tensor cores (bf16x3 splits everywhere).
// CTA = 64 q rows (4 warps x m16), key chunks of 64, 3-stage cp.async.
// SINGLE merged launch: blockIdx.x < NGLOB -> global attention (long-pole
// CTAs scheduled first), else local block attention.
// ============================================================================
#define ASTB 32768
#define ATT_SMEM (3*ASTB)
#define NGLOB 64

__global__ void __launch_bounds__(128) attn_tc(const float* __restrict__ mask)
{
    extern __shared__ char smem[];
    const uint32_t sb = smem_u32(smem);
    const int tid  = threadIdx.x;
    const int lane = tid & 31;
    const int w    = tid >> 5;

    const bf16 *qb, *kg, *vg, *kl, *vl;
    const float* mrow;
    bf16* outC;
    size_t outrow0;
    float ps;
    int nch;

    if (blockIdx.x < NGLOB) {
        int bi = blockIdx.x;
        int qt = bi & 1;  bi >>= 1;
        int h  = bi & 15;
        int b  = bi >> 4;
        size_t bh = (size_t)(b*HH + h);
        qb = d_gq2 + (bh*GG + qt*64)*128;
        kg = d_gk2 + bh*GG*128;
        vg = d_gv2 + bh*GG*128;
        kl = d_lk2 + bh*SS*128;
        vl = d_lv2 + bh*SS*128;
        mrow = mask + b*SS;
        outC = d_Cg2 + (size_t)(h*64);
        outrow0 = (size_t)b*GG + qt*64;
        ps = 0.125f; nch = 130;
    } else {
        int bi = blockIdx.x - NGLOB;
        int qt = bi & 7;  bi >>= 3;
        int n  = bi & 15; bi >>= 4;
        int h  = bi & 15;
        int b  = bi >> 4;
        size_t bh = (size_t)(b*HH + h);
        qb = d_lq2 + (bh*SS + n*512 + qt*64)*128;
        kg = d_gk2 + bh*GG*128;
        vg = d_gv2 + bh*GG*128;
        kl = d_lk2 + (bh*SS + n*512)*128;
        vl = d_lv2 + (bh*SS + n*512)*128;
        mrow = mask + b*SS + n*512;
        outC = d_C2 + (size_t)(h*64);
        outrow0 = (size_t)b*SS + n*512 + qt*64;
        ps = 1.0f; nch = 10;
    }

    // ---- stage Q into buffer 0, ldmatrix to registers ----
    {
        int r = tid;
        const bf16* src = qb + (r & 63)*128 + (r >> 6)*64;
        uint32_t dst = sb + r*128;
#pragma unroll
        for (int u = 0; u < 8; ++u)
            asm volatile("cp.async.cg.shared.global [%0], [%1], 16;"
                         :: "r"(dst + ((u*16) ^ ((r & 7)*16))), "l"(src + u*8));
        asm volatile("cp.async.commit_group;" ::: "memory");
        asm volatile("cp.async.wait_group 0;" ::: "memory");
        __syncthreads();
    }
    uint32_t qh[4][4], ql[4][4];
    {
        const int arow = w*16 + (lane & 15);
        const int akb  = lane >> 4;
#pragma unroll
        for (int ks = 0; ks < 4; ++ks) {
            uint32_t off = (uint32_t)((ks*2 + akb)*16);
            ldsm_x4(qh[ks], sb + arow*128 + (off ^ ((arow & 7)*16)));
            int arl = arow + 64;
            ldsm_x4(ql[ks], sb + arl*128  + (off ^ ((arl & 7)*16)));
        }
    }
    __syncthreads();

    // ---- pipeline K/V chunks ----
    auto load_chunk = [&](int c, int stage) {
        const bf16 *ksrc, *vsrc;
        if (c < 2) { ksrc = kg + (size_t)c*64*128;     vsrc = vg + (size_t)c*64*128; }
        else       { ksrc = kl + (size_t)(c-2)*64*128; vsrc = vl + (size_t)(c-2)*64*128; }
        int r = tid;
        const bf16* sk = ksrc + (r & 63)*128 + (r >> 6)*64;
        const bf16* sv = vsrc + (r & 63)*128 + (r >> 6)*64;
        uint32_t dK = sb + stage*ASTB + r*128;
        uint32_t dV = dK + 16384;
#pragma unroll
        for (int u = 0; u < 8; ++u)
            asm volatile("cp.async.cg.shared.global [%0], [%1], 16;"
                         :: "r"(dK + ((u*16) ^ ((r & 7)*16))), "l"(sk + u*8));
#pragma unroll
        for (int u = 0; u < 8; ++u)
            asm volatile("cp.async.cg.shared.global [%0], [%1], 16;"
                         :: "r"(dV + ((u*16) ^ ((r & 7)*16))), "l"(sv + u*8));
        asm volatile("cp.async.commit_group;" ::: "memory");
    };

    load_chunk(0, 0);
    load_chunk(1, 1);

    float m0r = -1e30f, m1r = -1e30f, l0r = 0.f, l1r = 0.f;
    float oacc[8][4];
#pragma unroll
    for (int j = 0; j < 8; ++j)
#pragma unroll
        for (int e = 0; e < 4; ++e) oacc[j][e] = 0.f;

    const int g     = lane >> 3;
    const int brow0 = (g >> 1)*8 + (lane & 7);
    const int bkb   = g & 1;
    const int vrow0 = (g & 1)*8 + (lane & 7);
    const int vcol  = (g >> 1)*16;

    for (int c = 0; c < nch; ++c) {
        if (c < nch-1) asm volatile("cp.async.wait_group 1;" ::: "memory");
        else           asm volatile("cp.async.wait_group 0;" ::: "memory");
        __syncthreads();
        if (c + 2 < nch) load_chunk(c+2, (c+2) % 3);

        const uint32_t Kb = sb + (c % 3)*ASTB;
        const uint32_t Vb = Kb + 16384;

        // ---- scores (Qhi.Khi + Qlo.Khi + Qhi.Klo) ----
        float sacc[8][4];
#pragma unroll
        for (int j = 0; j < 8; ++j)
#pragma unroll
            for (int e = 0; e < 4; ++e) sacc[j][e] = 0.f;

#pragma unroll
        for (int ks = 0; ks < 4; ++ks) {
            uint32_t bfh[4][4];
#pragma unroll
            for (int u = 0; u < 4; ++u) {
                int row = brow0 + u*16;
                uint32_t off = (uint32_t)((ks*2 + bkb)*16);
                ldsm_x4(bfh[u], Kb + row*128 + (off ^ ((row & 7)*16)));
            }
#pragma unroll
            for (int j = 0; j < 8; ++j) {
                mma_bf16(sacc[j], qh[ks], &bfh[j>>1][(j&1)*2]);
                mma_bf16(sacc[j], ql[ks], &bfh[j>>1][(j&1)*2]);
            }
            uint32_t bfl[4][4];
#pragma unroll
            for (int u = 0; u < 4; ++u) {
                int row = brow0 + u*16 + 64;
                uint32_t off = (uint32_t)((ks*2 + bkb)*16);
                ldsm_x4(bfl[u], Kb + row*128 + (off ^ ((row & 7)*16)));
            }
#pragma unroll
            for (int j = 0; j < 8; ++j)
                mma_bf16(sacc[j], qh[ks], &bfl[j>>1][(j&1)*2]);
        }

        // ---- mask + online softmax ----
        float mx0 = -1e30f, mx1 = -1e30f;
        const int kb0 = (c - 2)*64 + (lane & 3)*2;
#pragma unroll
        for (int j = 0; j < 8; ++j) {
            float mkx = 0.f, mky = 0.f;
            if (c >= 2) {
                float2 mm = __ldg((const float2*)(mrow + kb0 + j*8));
                mkx = mm.x; mky = mm.y;
            }
            sacc[j][0] = fmaf(sacc[j][0], ps, mkx);
            sacc[j][1] = fmaf(sacc[j][1], ps, mky);
            sacc[j][2] = fmaf(sacc[j][2], ps, mkx);
            sacc[j][3] = fmaf(sacc[j][3], ps, mky);
            mx0 = fmaxf(mx0, fmaxf(sacc[j][0], sacc[j][1]));
            mx1 = fmaxf(mx1, fmaxf(sacc[j][2], sacc[j][3]));
        }
        mx0 = fmaxf(mx0, __shfl_xor_sync(0xffffffffu, mx0, 1));
        mx0 = fmaxf(mx0, __shfl_xor_sync(0xffffffffu, mx0, 2));
        mx1 = fmaxf(mx1, __shfl_xor_sync(0xffffffffu, mx1, 1));
        mx1 = fmaxf(mx1, __shfl_xor_sync(0xffffffffu, mx1, 2));

        float mn0 = fmaxf(m0r, mx0), mn1 = fmaxf(m1r, mx1);
        float a0 = __expf(m0r - mn0), a1 = __expf(m1r - mn1);
        m0r = mn0; m1r = mn1;

        float sum0 = 0.f, sum1 = 0.f;
#pragma unroll
        for (int j = 0; j < 8; ++j) {
            sacc[j][0] = __expf(sacc[j][0] - mn0);
            sacc[j][1] = __expf(sacc[j][1] - mn0);
            sacc[j][2] = __expf(sacc[j][2] - mn1);
            sacc[j][3] = __expf(sacc[j][3] - mn1);
            sum0 += sacc[j][0] + sacc[j][1];
            sum1 += sacc[j][2] + sacc[j][3];
        }
        sum0 += __shfl_xor_sync(0xffffffffu, sum0, 1);
        sum0 += __shfl_xor_sync(0xffffffffu, sum0, 2);
        sum1 += __shfl_xor_sync(0xffffffffu, sum1, 1);
        sum1 += __shfl_xor_sync(0xffffffffu, sum1, 2);
        l0r = l0r*a0 + sum0;
        l1r = l1r*a1 + sum1;
#pragma unroll
        for (int j = 0; j < 8; ++j) {
            oacc[j][0] *= a0; oacc[j][1] *= a0;
            oacc[j][2] *= a1; oacc[j][3] *= a1;
        }

        // ---- P fragments (register-local hi/lo split) + PV ----
#pragma unroll
        for (int kv = 0; kv < 4; ++kv) {
            uint32_t pah[4], pal[4];
            pah[0] = pack_hi(sacc[2*kv][0],   sacc[2*kv][1]);
            pah[1] = pack_hi(sacc[2*kv][2],   sacc[2*kv][3]);
            pah[2] = pack_hi(sacc[2*kv+1][0], sacc[2*kv+1][1]);
            pah[3] = pack_hi(sacc[2*kv+1][2], sacc[2*kv+1][3]);
            pal[0] = pack_lo(sacc[2*kv][0],   sacc[2*kv][1]);
            pal[1] = pack_lo(sacc[2*kv][2],   sacc[2*kv][3]);
            pal[2] = pack_lo(sacc[2*kv+1][0], sacc[2*kv+1][1]);
            pal[3] = pack_lo(sacc[2*kv+1][2], sacc[2*kv+1][3]);

            uint32_t vfh[4][4];
#pragma unroll
            for (int dg = 0; dg < 4; ++dg) {
                int row = kv*16 + vrow0;
                uint32_t off = (uint32_t)(dg*32 + vcol);
                ldsm_x4_t(vfh[dg], Vb + row*128 + (off ^ ((row & 7)*16)));
            }
#pragma unroll
            for (int j = 0; j < 8; ++j) {
                mma_bf16(oacc[j], pah, &vfh[j>>1][(j&1)*2]);
                mma_bf16(oacc[j], pal, &vfh[j>>1][(j&1)*2]);
            }
            uint32_t vfl[4][4];
#pragma unroll
            for (int dg = 0; dg < 4; ++dg) {
                int row = kv*16 + vrow0 + 64;
                uint32_t off = (uint32_t)(dg*32 + vcol);
                ldsm_x4_t(vfl[dg], Vb + row*128 + (off ^ ((row & 7)*16)));
            }
#pragma unroll
            for (int j = 0; j < 8; ++j)
                mma_bf16(oacc[j], pah, &vfl[j>>1][(j&1)*2]);
        }
    }

    // ---- epilogue: normalize, hi/lo split, write ctx ----
    const float inv0 = 1.0f / l0r;
    const float inv1 = 1.0f / l1r;
    const size_t row0 = outrow0 + w*16 + (lane >> 2);
    const size_t row1 = row0 + 8;
#pragma unroll
    for (int j = 0; j < 8; ++j) {
        const int col = j*8 + (lane & 3)*2;
        float x0 = oacc[j][0]*inv0, y0 = oacc[j][1]*inv0;
        float x1 = oacc[j][2]*inv1, y1 = oacc[j][3]*inv1;
        bf16* p0 = outC + row0*2048 + col;
        bf16* p1 = outC + row1*2048 + col;
        *(uint32_t*)p0          = pack_hi(x0, y0);
        *(uint32_t*)(p0 + 1024) = pack_lo(x0, y0);
        *(uint32_t*)p1          = pack_hi(x1, y1);
        *(uint32_t*)(p1 + 1024) = pack_lo(x1, y1);
    }
}

// ============================================================================
extern "C" void kernel_launch(void* const* d_in, const int* in_sizes, int n_in,
                              void* d_out, int out_size) {
    (void)in_sizes; (void)n_in; (void)out_size;
    const float* Q    = (const float*)d_in[0];
    const float* K    = (const float*)d_in[1];
    const float* V    = (const float*)d_in[2];
    const float* Gt   = (const float*)d_in[3];
    const float* mask = (const float*)d_in[4];
    const float* Wq = (const float*)d_in[5];
    const float* bq = (const float*)d_in[6];
    const float* Wk = (const float*)d_in[7];
    const float* bk = (const float*)d_in[8];
    const float* Wv = (const float*)d_in[9];
    const float* bv = (const float*)d_in[10];
    const float* Wo = (const float*)d_in[11];
    const float* bo = (const float*)d_in[12];
    float* out = (float*)d_out;

    void *pQ2, *pK2, *pV2, *pG2, *pC2, *pCg2, *pWq2, *pWk2, *pWv2, *pWo2;
    cudaGetSymbolAddress(&pQ2,  d_Q2);
    cudaGetSymbolAddress(&pK2,  d_K2);
    cudaGetSymbolAddress(&pV2,  d_V2);
    cudaGetSymbolAddress(&pG2,  d_G2);
    cudaGetSymbolAddress(&pC2,  d_C2);
    cudaGetSymbolAddress(&pCg2, d_Cg2);
    cudaGetSymbolAddress(&pWq2, d_Wq2);
    cudaGetSymbolAddress(&pWk2, d_Wk2);
    cudaGetSymbolAddress(&pWv2, d_Wv2);
    cudaGetSymbolAddress(&pWo2, d_Wo2);

    cudaFuncSetAttribute(gemm_tc, cudaFuncAttributeMaxDynamicSharedMemorySize, GEMM_SMEM);
    cudaFuncSetAttribute(attn_tc, cudaFuncAttributeMaxDynamicSharedMemorySize, ATT_SMEM);

    typedef const bf16* bfp;
    typedef bf16* bfpw;

    // operand conversions
    conv_split<<<dim3(1024, 1, 4), 256>>>(Wq, Wk, Wv, Wo,
                                          (bfpw)pWq2, (bfpw)pWk2, (bfpw)pWv2, (bfpw)pWo2);
    conv_split<<<dim3(16384, 1, 3), 256>>>(Q, K, V, nullptr,
                                           (bfpw)pQ2, (bfpw)pK2, (bfpw)pV2, nullptr);
    conv_split<<<dim3(256, 1, 1), 256>>>(Gt, nullptr, nullptr, nullptr,
                                         (bfpw)pG2, nullptr, nullptr, nullptr);

    // projections (big + appended global rows), head-split bf16 hi|lo out
    gemm_tc<<<dim3(130, 8, 3), 256, GEMM_SMEM>>>(
        (bfp)pQ2, (bfp)pK2, (bfp)pV2, (bfp)pG2,
        (bfp)pWq2, (bfp)pWk2, (bfp)pWv2,
        bq, bk, bv, 128, 0, nullptr);

    // attention: single merged launch, global long-pole CTAs first
    attn_tc<<<NGLOB + 4096, 128, ATT_SMEM>>>(mask);

    // output projection (big ctx + appended global ctx) -> fp32 out
    gemm_tc<<<dim3(130, 8, 1), 256, GEMM_SMEM>>>(
        (bfp)pC2, nullptr, nullptr, (bfp)pCg2,
        (bfp)pWo2, nullptr, nullptr,
        bo, nullptr, nullptr, 128, 2, out);
}

// round 6
// speedup vs baseline: 3.6630x; 1.1150x over previous
#include <cuda_runtime.h>
#include <cuda_bf16.h>
#include <math.h>
#include <stdint.h>

// ---------------- problem constants ----------------
#define BB   2
#define SS   8192
#define DD   1024
#define HH   16
#define GG   128

typedef __nv_bfloat16 bf16;
typedef __nv_bfloat162 bf162;

// ---------------- bf16 [hi|lo] GEMM operands ----------------
__device__ bf16 d_Q2 [(size_t)16384*2048];
__device__ bf16 d_K2 [(size_t)16384*2048];
__device__ bf16 d_V2 [(size_t)16384*2048];
__device__ bf16 d_G2 [(size_t)256*2048];
__device__ bf16 d_C2 [(size_t)16384*2048];   // attention ctx (local), hi|lo
__device__ bf16 d_Cg2[(size_t)256*2048];     // attention ctx (global), hi|lo
__device__ bf16 d_Wq2[(size_t)1024*2048];
__device__ bf16 d_Wk2[(size_t)1024*2048];
__device__ bf16 d_Wv2[(size_t)1024*2048];
__device__ bf16 d_Wo2[(size_t)1024*2048];

// head-split projected tensors, bf16, row = token, 128 cols = [hi(64)|lo(64)]
__device__ bf16 d_lq2[(size_t)BB*HH*SS*128];
__device__ bf16 d_lk2[(size_t)BB*HH*SS*128];
__device__ bf16 d_lv2[(size_t)BB*HH*SS*128];
__device__ bf16 d_gq2[(size_t)BB*HH*GG*128];
__device__ bf16 d_gk2[(size_t)BB*HH*GG*128];
__device__ bf16 d_gv2[(size_t)BB*HH*GG*128];

// ---------------- helpers ----------------
__device__ __forceinline__ uint32_t smem_u32(const void* p) {
    uint32_t a;
    asm("{ .reg .u64 t; cvta.to.shared.u64 t, %1; cvt.u32.u64 %0, t; }"
        : "=r"(a) : "l"(p));
    return a;
}
__device__ __forceinline__ void ldsm_x4(uint32_t* r, uint32_t addr) {
    asm volatile("ldmatrix.sync.aligned.m8n8.x4.shared.b16 {%0,%1,%2,%3}, [%4];"
                 : "=r"(r[0]), "=r"(r[1]), "=r"(r[2]), "=r"(r[3]) : "r"(addr));
}
__device__ __forceinline__ void ldsm_x4_t(uint32_t* r, uint32_t addr) {
    asm volatile("ldmatrix.sync.aligned.m8n8.x4.trans.shared.b16 {%0,%1,%2,%3}, [%4];"
                 : "=r"(r[0]), "=r"(r[1]), "=r"(r[2]), "=r"(r[3]) : "r"(addr));
}
__device__ __forceinline__ void mma_bf16(float* d, const uint32_t* a, const uint32_t* b) {
    asm volatile("mma.sync.aligned.m16n8k16.row.col.f32.bf16.bf16.f32 "
                 "{%0,%1,%2,%3}, {%4,%5,%6,%7}, {%8,%9}, {%0,%1,%2,%3};"
                 : "+f"(d[0]), "+f"(d[1]), "+f"(d[2]), "+f"(d[3])
                 : "r"(a[0]), "r"(a[1]), "r"(a[2]), "r"(a[3]),
                   "r"(b[0]), "r"(b[1]));
}
__device__ __forceinline__ uint32_t pack_hi(float x, float y) {
    bf162 t = __halves2bfloat162(__float2bfloat16(x), __float2bfloat16(y));
    return *(uint32_t*)&t;
}
__device__ __forceinline__ uint32_t pack_lo(float x, float y) {
    bf16 hx = __float2bfloat16(x), hy = __float2bfloat16(y);
    bf162 t = __halves2bfloat162(__float2bfloat16(x - __bfloat162float(hx)),
                                 __float2bfloat16(y - __bfloat162float(hy)));
    return *(uint32_t*)&t;
}

// ============================================================================
// conv_all: ONE launch converting every fp32 operand -> bf16 [hi|lo].
// grid.x flattened: [0,4096) weights (Wq,Wk,Wv,Wo), [4096,53248) Q/K/V,
// [53248,53504) G_tokens. One row (1024 fp32) per block, 256 threads.
// ============================================================================
__global__ void conv_all(const float* __restrict__ Q,  const float* __restrict__ K,
                         const float* __restrict__ V,  const float* __restrict__ Gt,
                         const float* __restrict__ Wq, const float* __restrict__ Wk,
                         const float* __restrict__ Wv, const float* __restrict__ Wo,
                         bf16* __restrict__ Q2, bf16* __restrict__ K2,
                         bf16* __restrict__ V2, bf16* __restrict__ G2,
                         bf16* __restrict__ Wq2, bf16* __restrict__ Wk2,
                         bf16* __restrict__ Wv2, bf16* __restrict__ Wo2)
{
    int bx = blockIdx.x;
    const float* X; bf16* Y; size_t row;
    if (bx < 4096) {
        int z = bx >> 10; row = bx & 1023;
        X = (z==0)?Wq:(z==1)?Wk:(z==2)?Wv:Wo;
        Y = (z==0)?Wq2:(z==1)?Wk2:(z==2)?Wv2:Wo2;
    } else if (bx < 53248) {
        int i = bx - 4096; int z = i >> 14; row = i & 16383;
        X = (z==0)?Q:(z==1)?K:V;
        Y = (z==0)?Q2:(z==1)?K2:V2;
    } else {
        row = bx - 53248; X = Gt; Y = G2;
    }
    int col = threadIdx.x * 4;
    float4 x = *(const float4*)(X + row*1024 + col);
    bf16 h0 = __float2bfloat16(x.x), h1 = __float2bfloat16(x.y);
    bf16 h2 = __float2bfloat16(x.z), h3 = __float2bfloat16(x.w);
    bf162* ph = (bf162*)(Y + row*2048 + col);
    bf162* pl = (bf162*)(Y + row*2048 + 1024 + col);
    ph[0] = __halves2bfloat162(h0, h1);
    ph[1] = __halves2bfloat162(h2, h3);
    pl[0] = __halves2bfloat162(__float2bfloat16(x.x - __bfloat162float(h0)),
                               __float2bfloat16(x.y - __bfloat162float(h1)));
    pl[1] = __halves2bfloat162(__float2bfloat16(x.z - __bfloat162float(h2)),
                               __float2bfloat16(x.w - __bfloat162float(h3)));
}

// ============================================================================
// gemm_tc: C = (A . W^T + bias) * scale via bf16x3 on mma.sync (unchanged,
// Round-5 proven: tensor 73.9%, regs 128, 2 CTAs/SM).
// ============================================================================
#define NST  3
#define STB  32768
#define NCH  48
#define GEMM_SMEM (NST*STB)

__global__ void __launch_bounds__(256, 2) gemm_tc(
    const bf16* __restrict__ A0, const bf16* __restrict__ A1,
    const bf16* __restrict__ A2, const bf16* __restrict__ Ag,
    const bf16* __restrict__ W0, const bf16* __restrict__ W1,
    const bf16* __restrict__ W2,
    const float* __restrict__ Bi0, const float* __restrict__ Bi1,
    const float* __restrict__ Bi2,
    int nbig, int mode, float* __restrict__ outp)
{
    extern __shared__ char smem[];
    const uint32_t sb  = smem_u32(smem);
    const int tid  = threadIdx.x;
    const int wid  = tid >> 5;
    const int lane = tid & 31;
    const int z    = blockIdx.z;
    const int bx   = blockIdx.x;
    const bool big = bx < nbig;

    const bf16* A = big ? ((z==0)?A0:(z==1)?A1:A2) : Ag;
    const bf16* W = (z==0)?W0:(z==1)?W1:W2;
    const float* bias = (z==0)?Bi0:(z==1)?Bi1:Bi2;

    const int m0 = (big ? bx : bx - nbig) * 128;
    const int n0 = blockIdx.y * 128;
    const float scale = (mode == 0 && z == 0) ? 0.125f : 1.0f;

    const int      r0  = tid >> 3;
    const int      c16 = tid & 7;
    const uint32_t swo = (uint32_t)(tid*16) ^ ((uint32_t)(tid*2) & 0x70);
    const bf16* Abase = A + (size_t)(m0 + r0)*2048 + c16*8;
    const bf16* Wbase = W + (size_t)(n0 + r0)*2048 + c16*8;

    auto load_stage = [&](int stage, int c) {
        const int aIdx = (c < 16) ? c : c - 16;   // A: hi,hi,lo
        const int wIdx = (c < 32) ? c : c - 32;   // W: hi,lo,hi
        const bf16* ga = Abase + aIdx*64;
        const bf16* gw = Wbase + wIdx*64;
        const uint32_t smA = sb + stage*STB;
        const uint32_t smB = smA + 16384;
#pragma unroll
        for (int i = 0; i < 4; ++i)
            asm volatile("cp.async.cg.shared.global [%0], [%1], 16;"
                         :: "r"(smA + swo + i*4096), "l"(ga + (size_t)i*32*2048));
#pragma unroll
        for (int i = 0; i < 4; ++i)
            asm volatile("cp.async.cg.shared.global [%0], [%1], 16;"
                         :: "r"(smB + swo + i*4096), "l"(gw + (size_t)i*32*2048));
        asm volatile("cp.async.commit_group;" ::: "memory");
    };

    const int wr = wid & 3;
    const int wc = wid >> 2;
    const int arow = wr*32 + (lane & 15);
    const int akb  = lane >> 4;
    const int g    = lane >> 3;
    const int brow = wc*64 + (g >> 1)*8 + (lane & 7);
    const int bkb  = g & 1;

    float acc[2][8][4];
#pragma unroll
    for (int t = 0; t < 2; ++t)
#pragma unroll
        for (int j = 0; j < 8; ++j)
#pragma unroll
            for (int e = 0; e < 4; ++e) acc[t][j][e] = 0.f;

    load_stage(0, 0);
    load_stage(1, 1);

    for (int c = 0; c < NCH; ++c) {
        if (c < NCH-1) asm volatile("cp.async.wait_group 1;" ::: "memory");
        else           asm volatile("cp.async.wait_group 0;" ::: "memory");
        __syncthreads();
        if (c + 2 < NCH) load_stage((c+2) % NST, c+2);

        const uint32_t smA = sb + (c % NST)*STB;
        const uint32_t smB = smA + 16384;

#pragma unroll
        for (int ks = 0; ks < 4; ++ks) {
            const int kb = ks*2;
            uint32_t af[2][4];
#pragma unroll
            for (int t = 0; t < 2; ++t) {
                int row = arow + t*16;
                uint32_t off = (uint32_t)(row*128 + (kb + akb)*16);
                ldsm_x4(af[t], smA + (off ^ ((row & 7) * 16)));
            }
            uint32_t bf[4][4];
#pragma unroll
            for (int u = 0; u < 4; ++u) {
                int row = brow + u*16;
                uint32_t off = (uint32_t)(row*128 + (kb + bkb)*16);
                ldsm_x4(bf[u], smB + (off ^ ((row & 7) * 16)));
            }
#pragma unroll
            for (int t = 0; t < 2; ++t)
#pragma unroll
                for (int j = 0; j < 8; ++j)
                    mma_bf16(acc[t][j], af[t], &bf[j>>1][(j&1)*2]);
        }
    }
    __syncthreads();

    // ---- epilogue ----
#pragma unroll
    for (int t = 0; t < 2; ++t) {
        const int r1 = m0 + wr*32 + t*16 + (lane >> 2);
        const int r2 = r1 + 8;
#pragma unroll
        for (int j = 0; j < 8; ++j) {
            const int nb = n0 + wc*64 + j*8 + (lane & 3)*2;
            float2 bv = *(const float2*)(bias + nb);
            float2 v1, v2;
            v1.x = (acc[t][j][0] + bv.x) * scale;
            v1.y = (acc[t][j][1] + bv.y) * scale;
            v2.x = (acc[t][j][2] + bv.x) * scale;
            v2.y = (acc[t][j][3] + bv.y) * scale;
            if (mode == 2) {
                const size_t ro = big ? 0 : 16384;
                *(float2*)(outp + (ro + r1) * 1024 + nb) = v1;
                *(float2*)(outp + (ro + r2) * 1024 + nb) = v2;
            } else {
                bf16* T = big ? ((z==0)?d_lq2:(z==1)?d_lk2:d_lv2)
                              : ((z==0)?d_gq2:(z==1)?d_gk2:d_gv2);
                const int Lr = big ? SS : GG;
                const int h = nb >> 6;
                const int f = nb & 63;
                {
                    int b = r1 / Lr, s = r1 - b*Lr;
                    bf16* base = T + ((size_t)(b*HH + h)*Lr + s)*128 + f;
                    *(uint32_t*)base        = pack_hi(v1.x, v1.y);
                    *(uint32_t*)(base + 64) = pack_lo(v1.x, v1.y);
                }
                {
                    int b = r2 / Lr, s = r2 - b*Lr;
                    bf16* base = T + ((size_t)(b*HH + h)*Lr + s)*128 + f;
                    *(uint32_t*)base        = pack_hi(v2.x, v2.y);
                    *(uint32_t*)(base + 64) = pack_lo(v2.x, v2.y);
                }
            }
        }
    }
}

// ============================================================================
// attn_tc: flash attention on tensor cores (bf16x3), merged launch, 256 thr.
//  blockIdx.x <  NGLOB : global attention, 64 q rows, warps 0-3 only
//                        (warps 4-7 exit after Q staging), 130 key chunks.
//  blockIdx.x >= NGLOB : local block attention, 128 q rows, 8 warps sharing
//                        the K/V pipeline (halves K/V global traffic).
// Q staged into stage buffers 0..qtiles-1 before the pipeline starts.
// ============================================================================
#define ASTB 32768
#define ATT_SMEM (3*ASTB)
#define NGLOB 64

__global__ void __launch_bounds__(256) attn_tc(const float* __restrict__ mask)
{
    extern __shared__ char smem[];
    const uint32_t sb = smem_u32(smem);
    const int tid  = threadIdx.x;
    const int lane = tid & 31;
    const int w    = tid >> 5;

    const bf16 *qb, *kg, *vg, *kl, *vl;
    const float* mrow;
    bf16* outC;
    size_t outrow0;
    float ps;
    int nch, nact, qtiles;

    if (blockIdx.x < NGLOB) {
        int bi = blockIdx.x;
        int qt = bi & 1;  bi >>= 1;
        int h  = bi & 15;
        int b  = bi >> 4;
        size_t bh = (size_t)(b*HH + h);
        qb = d_gq2 + (bh*GG + qt*64)*128;
        kg = d_gk2 + bh*GG*128;
        vg = d_gv2 + bh*GG*128;
        kl = d_lk2 + bh*SS*128;
        vl = d_lv2 + bh*SS*128;
        mrow = mask + b*SS;
        outC = d_Cg2 + (size_t)(h*64);
        outrow0 = (size_t)b*GG + qt*64;
        ps = 0.125f; nch = 130; nact = 128; qtiles = 1;
    } else {
        int bi = blockIdx.x - NGLOB;
        int qt = bi & 3;  bi >>= 2;
        int n  = bi & 15; bi >>= 4;
        int h  = bi & 15;
        int b  = bi >> 4;
        size_t bh = (size_t)(b*HH + h);
        qb = d_lq2 + (bh*SS + n*512 + qt*128)*128;
        kg = d_gk2 + bh*GG*128;
        vg = d_gv2 + bh*GG*128;
        kl = d_lk2 + (bh*SS + n*512)*128;
        vl = d_lv2 + (bh*SS + n*512)*128;
        mrow = mask + b*SS + n*512;
        outC = d_C2 + (size_t)(h*64);
        outrow0 = (size_t)b*SS + n*512 + qt*128;
        ps = 1.0f; nch = 10; nact = 256; qtiles = 2;
    }

    // ---- stage Q: qtiles x (64 rows, 32KB tile) into stages 0..qtiles-1 ----
    {
        const int nu = qtiles * 1024;
        for (int u = tid; u < nu; u += 256) {
            int t = u >> 10;
            int v = u & 1023;
            uint32_t sw = (uint32_t)((v*16) ^ (((v>>3)&7)*16));
            const bf16* s = qb + (size_t)(t*64 + ((v>>3)&63))*128 + (v>>9)*64 + (v&7)*8;
            asm volatile("cp.async.cg.shared.global [%0], [%1], 16;"
                         :: "r"(sb + t*ASTB + sw), "l"(s));
        }
        asm volatile("cp.async.commit_group;" ::: "memory");
        asm volatile("cp.async.wait_group 0;" ::: "memory");
        __syncthreads();
    }
    uint32_t qh[4][4], ql[4][4];
    if (w < qtiles*4) {
        const uint32_t tb = sb + (w>>2)*ASTB;
        const int arow = (w&3)*16 + (lane & 15);
        const int akb  = lane >> 4;
#pragma unroll
        for (int ks = 0; ks < 4; ++ks) {
            uint32_t off = (uint32_t)((ks*2 + akb)*16);
            ldsm_x4(qh[ks], tb + arow*128 + (off ^ ((arow & 7)*16)));
            int arl = arow + 64;
            ldsm_x4(ql[ks], tb + arl*128  + (off ^ ((arl & 7)*16)));
        }
    }
    __syncthreads();
    if (w >= qtiles*4) return;   // global CTAs: warps 4-7 retire

    // ---- K/V chunk pipeline ----
    auto load_chunk = [&](int c, int stage) {
        const bf16 *ksrc, *vsrc;
        if (c < 2) { ksrc = kg + (size_t)c*8192;     vsrc = vg + (size_t)c*8192; }
        else       { ksrc = kl + (size_t)(c-2)*8192; vsrc = vl + (size_t)(c-2)*8192; }
        const uint32_t dK = sb + stage*ASTB;
        const uint32_t dV = dK + 16384;
        for (int u = tid; u < 1024; u += nact) {
            uint32_t sw = (uint32_t)((u*16) ^ (((u>>3)&7)*16));
            size_t so = (size_t)((u>>3)&63)*128 + (u>>9)*64 + (u&7)*8;
            asm volatile("cp.async.cg.shared.global [%0], [%1], 16;"
                         :: "r"(dK + sw), "l"(ksrc + so));
            asm volatile("cp.async.cg.shared.global [%0], [%1], 16;"
                         :: "r"(dV + sw), "l"(vsrc + so));
        }
        asm volatile("cp.async.commit_group;" ::: "memory");
    };

    load_chunk(0, 0);
    load_chunk(1, 1);

    float m0r = -1e30f, m1r = -1e30f, l0r = 0.f, l1r = 0.f;
    float oacc[8][4];
#pragma unroll
    for (int j = 0; j < 8; ++j)
#pragma unroll
        for (int e = 0; e < 4; ++e) oacc[j][e] = 0.f;

    const int g     = lane >> 3;
    const int brow0 = (g >> 1)*8 + (lane & 7);
    const int bkb   = g & 1;
    const int vrow0 = (g & 1)*8 + (lane & 7);
    const int vcol  = (g >> 1)*16;

    for (int c = 0; c < nch; ++c) {
        if (c < nch-1) asm volatile("cp.async.wait_group 1;" ::: "memory");
        else           asm volatile("cp.async.wait_group 0;" ::: "memory");
        __syncthreads();
        if (c + 2 < nch) load_chunk(c+2, (c+2) % 3);

        const uint32_t Kb = sb + (c % 3)*ASTB;
        const uint32_t Vb = Kb + 16384;

        // ---- scores (Qhi.Khi + Qlo.Khi + Qhi.Klo) ----
        float sacc[8][4];
#pragma unroll
        for (int j = 0; j < 8; ++j)
#pragma unroll
            for (int e = 0; e < 4; ++e) sacc[j][e] = 0.f;

#pragma unroll
        for (int ks = 0; ks < 4; ++ks) {
            uint32_t bfh[4][4];
#pragma unroll
            for (int u = 0; u < 4; ++u) {
                int row = brow0 + u*16;
                uint32_t off = (uint32_t)((ks*2 + bkb)*16);
                ldsm_x4(bfh[u], Kb + row*128 + (off ^ ((row & 7)*16)));
            }
#pragma unroll
            for (int j = 0; j < 8; ++j) {
                mma_bf16(sacc[j], qh[ks], &bfh[j>>1][(j&1)*2]);
                mma_bf16(sacc[j], ql[ks], &bfh[j>>1][(j&1)*2]);
            }
            uint32_t bfl[4][4];
#pragma unroll
            for (int u = 0; u < 4; ++u) {
                int row = brow0 + u*16 + 64;
                uint32_t off = (uint32_t)((ks*2 + bkb)*16);
                ldsm_x4(bfl[u], Kb + row*128 + (off ^ ((row & 7)*16)));
            }
#pragma unroll
            for (int j = 0; j < 8; ++j)
                mma_bf16(sacc[j], qh[ks], &bfl[j>>1][(j&1)*2]);
        }

        // ---- mask + online softmax ----
        float mx0 = -1e30f, mx1 = -1e30f;
        const int kb0 = (c - 2)*64 + (lane & 3)*2;
#pragma unroll
        for (int j = 0; j < 8; ++j) {
            float mkx = 0.f, mky = 0.f;
            if (c >= 2) {
                float2 mm = __ldg((const float2*)(mrow + kb0 + j*8));
                mkx = mm.x; mky = mm.y;
            }
            sacc[j][0] = fmaf(sacc[j][0], ps, mkx);
            sacc[j][1] = fmaf(sacc[j][1], ps, mky);
            sacc[j][2] = fmaf(sacc[j][2], ps, mkx);
            sacc[j][3] = fmaf(sacc[j][3], ps, mky);
            mx0 = fmaxf(mx0, fmaxf(sacc[j][0], sacc[j][1]));
            mx1 = fmaxf(mx1, fmaxf(sacc[j][2], sacc[j][3]));
        }
        mx0 = fmaxf(mx0, __shfl_xor_sync(0xffffffffu, mx0, 1));
        mx0 = fmaxf(mx0, __shfl_xor_sync(0xffffffffu, mx0, 2));
        mx1 = fmaxf(mx1, __shfl_xor_sync(0xffffffffu, mx1, 1));
        mx1 = fmaxf(mx1, __shfl_xor_sync(0xffffffffu, mx1, 2));

        float mn0 = fmaxf(m0r, mx0), mn1 = fmaxf(m1r, mx1);
        float a0 = __expf(m0r - mn0), a1 = __expf(m1r - mn1);
        m0r = mn0; m1r = mn1;

        float sum0 = 0.f, sum1 = 0.f;
#pragma unroll
        for (int j = 0; j < 8; ++j) {
            sacc[j][0] = __expf(sacc[j][0] - mn0);
            sacc[j][1] = __expf(sacc[j][1] - mn0);
            sacc[j][2] = __expf(sacc[j][2] - mn1);
            sacc[j][3] = __expf(sacc[j][3] - mn1);
            sum0 += sacc[j][0] + sacc[j][1];
            sum1 += sacc[j][2] + sacc[j][3];
        }
        sum0 += __shfl_xor_sync(0xffffffffu, sum0, 1);
        sum0 += __shfl_xor_sync(0xffffffffu, sum0, 2);
        sum1 += __shfl_xor_sync(0xffffffffu, sum1, 1);
        sum1 += __shfl_xor_sync(0xffffffffu, sum1, 2);
        l0r = l0r*a0 + sum0;
        l1r = l1r*a1 + sum1;
#pragma unroll
        for (int j = 0; j < 8; ++j) {
            oacc[j][0] *= a0; oacc[j][1] *= a0;
            oacc[j][2] *= a1; oacc[j][3] *= a1;
        }

        // ---- P fragments (register-local hi/lo split) + PV ----
#pragma unroll
        for (int kv = 0; kv < 4; ++kv) {
            uint32_t pah[4], pal[4];
            pah[0] = pack_hi(sacc[2*kv][0],   sacc[2*kv][1]);
            pah[1] = pack_hi(sacc[2*kv][2],   sacc[2*kv][3]);
            pah[2] = pack_hi(sacc[2*kv+1][0], sacc[2*kv+1][1]);
            pah[3] = pack_hi(sacc[2*kv+1][2], sacc[2*kv+1][3]);
            pal[0] = pack_lo(sacc[2*kv][0],   sacc[2*kv][1]);
            pal[1] = pack_lo(sacc[2*kv][2],   sacc[2*kv][3]);
            pal[2] = pack_lo(sacc[2*kv+1][0], sacc[2*kv+1][1]);
            pal[3] = pack_lo(sacc[2*kv+1][2], sacc[2*kv+1][3]);

            uint32_t vfh[4][4];
#pragma unroll
            for (int dg = 0; dg < 4; ++dg) {
                int row = kv*16 + vrow0;
                uint32_t off = (uint32_t)(dg*32 + vcol);
                ldsm_x4_t(vfh[dg], Vb + row*128 + (off ^ ((row & 7)*16)));
            }
#pragma unroll
            for (int j = 0; j < 8; ++j) {
                mma_bf16(oacc[j], pah, &vfh[j>>1][(j&1)*2]);
                mma_bf16(oacc[j], pal, &vfh[j>>1][(j&1)*2]);
            }
            uint32_t vfl[4][4];
#pragma unroll
            for (int dg = 0; dg < 4; ++dg) {
                int row = kv*16 + vrow0 + 64;
                uint32_t off = (uint32_t)(dg*32 + vcol);
                ldsm_x4_t(vfl[dg], Vb + row*128 + (off ^ ((row & 7)*16)));
            }
#pragma unroll
            for (int j = 0; j < 8; ++j)
                mma_bf16(oacc[j], pah, &vfl[j>>1][(j&1)*2]);
        }
    }

    // ---- epilogue: normalize, hi/lo split, write ctx ----
    const float inv0 = 1.0f / l0r;
    const float inv1 = 1.0f / l1r;
    const size_t row0 = outrow0 + (w>>2)*64 + (w&3)*16 + (lane >> 2);
    const size_t row1 = row0 + 8;
#pragma unroll
    for (int j = 0; j < 8; ++j) {
        const int col = j*8 + (lane & 3)*2;
        float x0 = oacc[j][0]*inv0, y0 = oacc[j][1]*inv0;
        float x1 = oacc[j][2]*inv1, y1 = oacc[j][3]*inv1;
        bf16* p0 = outC + row0*2048 + col;
        bf16* p1 = outC + row1*2048 + col;
        *(uint32_t*)p0          = pack_hi(x0, y0);
        *(uint32_t*)(p0 + 1024) = pack_lo(x0, y0);
        *(uint32_t*)p1          = pack_hi(x1, y1);
        *(uint32_t*)(p1 + 1024) = pack_lo(x1, y1);
    }
}

// ============================================================================
extern "C" void kernel_launch(void* const* d_in, const int* in_sizes, int n_in,
                              void* d_out, int out_size) {
    (void)in_sizes; (void)n_in; (void)out_size;
    const float* Q    = (const float*)d_in[0];
    const float* K    = (const float*)d_in[1];
    const float* V    = (const float*)d_in[2];
    const float* Gt   = (const float*)d_in[3];
    const float* mask = (const float*)d_in[4];
    const float* Wq = (const float*)d_in[5];
    const float* bq = (const float*)d_in[6];
    const float* Wk = (const float*)d_in[7];
    const float* bk = (const float*)d_in[8];
    const float* Wv = (const float*)d_in[9];
    const float* bv = (const float*)d_in[10];
    const float* Wo = (const float*)d_in[11];
    const float* bo = (const float*)d_in[12];
    float* out = (float*)d_out;

    void *pQ2, *pK2, *pV2, *pG2, *pC2, *pCg2, *pWq2, *pWk2, *pWv2, *pWo2;
    cudaGetSymbolAddress(&pQ2,  d_Q2);
    cudaGetSymbolAddress(&pK2,  d_K2);
    cudaGetSymbolAddress(&pV2,  d_V2);
    cudaGetSymbolAddress(&pG2,  d_G2);
    cudaGetSymbolAddress(&pC2,  d_C2);
    cudaGetSymbolAddress(&pCg2, d_Cg2);
    cudaGetSymbolAddress(&pWq2, d_Wq2);
    cudaGetSymbolAddress(&pWk2, d_Wk2);
    cudaGetSymbolAddress(&pWv2, d_Wv2);
    cudaGetSymbolAddress(&pWo2, d_Wo2);

    cudaFuncSetAttribute(gemm_tc, cudaFuncAttributeMaxDynamicSharedMemorySize, GEMM_SMEM);
    cudaFuncSetAttribute(attn_tc, cudaFuncAttributeMaxDynamicSharedMemorySize, ATT_SMEM);

    typedef const bf16* bfp;
    typedef bf16* bfpw;

    // all conversions in ONE launch
    conv_all<<<53504, 256>>>(Q, K, V, Gt, Wq, Wk, Wv, Wo,
                             (bfpw)pQ2, (bfpw)pK2, (bfpw)pV2, (bfpw)pG2,
                             (bfpw)pWq2, (bfpw)pWk2, (bfpw)pWv2, (bfpw)pWo2);

    // projections (big + appended global rows), head-split bf16 hi|lo out
    gemm_tc<<<dim3(130, 8, 3), 256, GEMM_SMEM>>>(
        (bfp)pQ2, (bfp)pK2, (bfp)pV2, (bfp)pG2,
        (bfp)pWq2, (bfp)pWk2, (bfp)pWv2,
        bq, bk, bv, 128, 0, nullptr);

    // attention: merged launch; global long-pole CTAs first; local CTAs
    // now cover 128 q rows each (halved K/V traffic)
    attn_tc<<<NGLOB + 2048, 256, ATT_SMEM>>>(mask);

    // output projection (big ctx + appended global ctx) -> fp32 out
    gemm_tc<<<dim3(130, 8, 1), 256, GEMM_SMEM>>>(
        (bfp)pC2, nullptr, nullptr, (bfp)pCg2,
        (bfp)pWo2, nullptr, nullptr,
        bo, nullptr, nullptr, 128, 2, out);
}